// round 1
// baseline (speedup 1.0000x reference)
#include <cuda_runtime.h>
#include <cuda_bf16.h>

typedef unsigned int uint32;

// ---------------- problem constants ----------------
constexpr int N_EL    = 300000;
constexpr int SENS    = 64;
constexpr int TICKS   = 1024;
constexpr int HID     = 128;

// ---------------- scratch: response_of_sensors as bf16 [N, 64] ----------------
// stored as uint32 = bf16x2 pairs -> [N, 32] u32
__device__ uint32 g_R32[(size_t)N_EL * (SENS / 2)];

// ---------------- MLP kernel (bf16 mma.sync) ----------------
// Block: 512 threads (16 warps), M = 256 electrons/block, warp owns 16 rows.
constexpr int KP   = 136;   // padded K stride in bf16 elems (conflict-free frag loads)
constexpr int KPW  = KP / 2;
constexpr int MROW = 256;

constexpr int OFF_W2T = 0;                          // [128][KP] bf16 (transposed W2: [n][k])
constexpr int OFF_W3T = OFF_W2T + HID  * KP * 2;    // [64][KP]  bf16 (transposed W3)
constexpr int OFF_H   = OFF_W3T + SENS * KP * 2;    // [256][KP] bf16 (h1 then h2, per-warp rows)
constexpr int OFF_W1  = OFF_H   + MROW * KP * 2;    // float[256]
constexpr int OFF_B1  = OFF_W1  + 256 * 4;          // float[128]
constexpr int OFF_B2  = OFF_B1  + 128 * 4;          // float[128]
constexpr int OFF_B3  = OFF_B2  + 128 * 4;          // float[64]
constexpr int OFF_XY  = OFF_B3  + 64 * 4;           // float2[256]
constexpr int SMEM_SZ = OFF_XY  + 256 * 8;          // ~126 KB

__device__ __forceinline__ void mma16816(float* c, uint32 a0, uint32 a1, uint32 a2, uint32 a3,
                                         uint32 b0, uint32 b1) {
    asm volatile(
        "mma.sync.aligned.m16n8k16.row.col.f32.bf16.bf16.f32 "
        "{%0,%1,%2,%3},{%4,%5,%6,%7},{%8,%9},{%0,%1,%2,%3};\n"
        : "+f"(c[0]), "+f"(c[1]), "+f"(c[2]), "+f"(c[3])
        : "r"(a0), "r"(a1), "r"(a2), "r"(a3), "r"(b0), "r"(b1));
}

__device__ __forceinline__ uint32 packbf2(float a, float b) {
    __nv_bfloat162 t = __floats2bfloat162_rn(a, b);   // .x = a (low), .y = b (high)
    return *reinterpret_cast<uint32*>(&t);
}

__global__ __launch_bounds__(512, 1)
void mlp_kernel(const float* __restrict__ photons,
                const float2* __restrict__ xy,
                const float* __restrict__ W1, const float* __restrict__ b1,
                const float* __restrict__ W2, const float* __restrict__ b2,
                const float* __restrict__ W3, const float* __restrict__ b3) {
    extern __shared__ unsigned char smem[];
    __nv_bfloat16* sW2t = reinterpret_cast<__nv_bfloat16*>(smem + OFF_W2T);
    __nv_bfloat16* sW3t = reinterpret_cast<__nv_bfloat16*>(smem + OFF_W3T);
    __nv_bfloat16* sH   = reinterpret_cast<__nv_bfloat16*>(smem + OFF_H);
    float* sW1 = reinterpret_cast<float*>(smem + OFF_W1);
    float* sB1 = reinterpret_cast<float*>(smem + OFF_B1);
    float* sB2 = reinterpret_cast<float*>(smem + OFF_B2);
    float* sB3 = reinterpret_cast<float*>(smem + OFF_B3);
    float2* sXY = reinterpret_cast<float2*>(smem + OFF_XY);

    const int tid = threadIdx.x;
    const int m0  = blockIdx.x * MROW;

    // ---- load weights / biases / inputs into shared ----
    for (int i = tid; i < 256; i += 512) sW1[i] = W1[i];
    for (int i = tid; i < 128; i += 512) { sB1[i] = b1[i]; sB2[i] = b2[i]; }
    for (int i = tid; i < 64;  i += 512) sB3[i] = b3[i];
    for (int i = tid; i < HID * HID; i += 512) {           // W2[k][n] -> sW2t[n][k]
        int k = i >> 7, n = i & 127;
        sW2t[n * KP + k] = __float2bfloat16_rn(W2[i]);
    }
    for (int i = tid; i < HID * SENS; i += 512) {          // W3[k][n] -> sW3t[n][k]
        int k = i >> 6, n = i & 63;
        sW3t[n * KP + k] = __float2bfloat16_rn(W3[i]);
    }
    for (int i = tid; i < MROW; i += 512) {
        int gr = m0 + i;
        sXY[i] = (gr < N_EL) ? xy[gr] : make_float2(0.f, 0.f);
    }
    __syncthreads();

    // ---- phase 1: h1 = relu(xy @ W1 + b1), fp32 SIMT -> bf16 shared ----
    uint32* sHw = reinterpret_cast<uint32*>(sH);
    for (int i = tid; i < MROW * 64; i += 512) {
        int m = i >> 6, j0 = (i & 63) * 2;
        float x = sXY[m].x, y = sXY[m].y;
        float v0 = fmaf(y, sW1[128 + j0],     fmaf(x, sW1[j0],     sB1[j0]));
        float v1 = fmaf(y, sW1[128 + j0 + 1], fmaf(x, sW1[j0 + 1], sB1[j0 + 1]));
        v0 = fmaxf(v0, 0.f); v1 = fmaxf(v1, 0.f);
        sHw[m * KPW + (j0 >> 1)] = packbf2(v0, v1);
    }
    __syncthreads();

    // ---- phase 2: h2 = relu(h1 @ W2 + b2) via mma, warp owns 16 rows ----
    const int wid = tid >> 5, lane = tid & 31;
    const int mb = wid * 16;
    const int g = lane >> 2, tg = lane & 3;
    const int row0 = mb + g, row1 = row0 + 8;

    {
        float acc[64];
        #pragma unroll
        for (int i = 0; i < 64; i++) acc[i] = 0.f;
        #pragma unroll
        for (int kt = 0; kt < 8; kt++) {
            int kc = kt * 16 + tg * 2;
            uint32 a0 = *reinterpret_cast<const uint32*>(sH + row0 * KP + kc);
            uint32 a1 = *reinterpret_cast<const uint32*>(sH + row1 * KP + kc);
            uint32 a2 = *reinterpret_cast<const uint32*>(sH + row0 * KP + kc + 8);
            uint32 a3 = *reinterpret_cast<const uint32*>(sH + row1 * KP + kc + 8);
            #pragma unroll
            for (int nt = 0; nt < 16; nt++) {
                const __nv_bfloat16* Bp = sW2t + (nt * 8 + g) * KP + kc;
                uint32 b0 = *reinterpret_cast<const uint32*>(Bp);
                uint32 b1r = *reinterpret_cast<const uint32*>(Bp + 8);
                mma16816(&acc[nt * 4], a0, a1, a2, a3, b0, b1r);
            }
        }
        #pragma unroll
        for (int nt = 0; nt < 16; nt++) {
            int c0 = nt * 8 + tg * 2;
            float v0 = fmaxf(acc[nt * 4 + 0] + sB2[c0],     0.f);
            float v1 = fmaxf(acc[nt * 4 + 1] + sB2[c0 + 1], 0.f);
            float v2 = fmaxf(acc[nt * 4 + 2] + sB2[c0],     0.f);
            float v3 = fmaxf(acc[nt * 4 + 3] + sB2[c0 + 1], 0.f);
            sHw[row0 * KPW + (c0 >> 1)] = packbf2(v0, v1);
            sHw[row1 * KPW + (c0 >> 1)] = packbf2(v2, v3);
        }
    }
    __syncwarp();

    // ---- phase 3: r = photons * sigmoid(h2 @ W3 + b3) -> bf16 global ----
    {
        float acc[32];
        #pragma unroll
        for (int i = 0; i < 32; i++) acc[i] = 0.f;
        #pragma unroll
        for (int kt = 0; kt < 8; kt++) {
            int kc = kt * 16 + tg * 2;
            uint32 a0 = *reinterpret_cast<const uint32*>(sH + row0 * KP + kc);
            uint32 a1 = *reinterpret_cast<const uint32*>(sH + row1 * KP + kc);
            uint32 a2 = *reinterpret_cast<const uint32*>(sH + row0 * KP + kc + 8);
            uint32 a3 = *reinterpret_cast<const uint32*>(sH + row1 * KP + kc + 8);
            #pragma unroll
            for (int nt = 0; nt < 8; nt++) {
                const __nv_bfloat16* Bp = sW3t + (nt * 8 + g) * KP + kc;
                uint32 b0 = *reinterpret_cast<const uint32*>(Bp);
                uint32 b1r = *reinterpret_cast<const uint32*>(Bp + 8);
                mma16816(&acc[nt * 4], a0, a1, a2, a3, b0, b1r);
            }
        }
        int gr0 = m0 + row0, gr1 = m0 + row1;
        float ph0 = (gr0 < N_EL) ? photons[gr0] : 0.f;
        float ph1 = (gr1 < N_EL) ? photons[gr1] : 0.f;
        #pragma unroll
        for (int nt = 0; nt < 8; nt++) {
            int c0 = nt * 8 + tg * 2;
            float s0 = 1.f / (1.f + __expf(-(acc[nt * 4 + 0] + sB3[c0])));
            float s1 = 1.f / (1.f + __expf(-(acc[nt * 4 + 1] + sB3[c0 + 1])));
            float s2 = 1.f / (1.f + __expf(-(acc[nt * 4 + 2] + sB3[c0])));
            float s3 = 1.f / (1.f + __expf(-(acc[nt * 4 + 3] + sB3[c0 + 1])));
            if (gr0 < N_EL) g_R32[gr0 * 32 + (c0 >> 1)] = packbf2(ph0 * s0, ph0 * s1);
            if (gr1 < N_EL) g_R32[gr1 * 32 + (c0 >> 1)] = packbf2(ph1 * s2, ph1 * s3);
        }
    }
}

// ---------------- output zeroing ----------------
__global__ void zero_kernel(float* __restrict__ out) {
    out[blockIdx.x * 1024 + threadIdx.x] = 0.f;
}

// ---------------- waveform scatter kernel ----------------
// grid (32 tick-blocks, 16 electron-slices). Block: 256 threads (8 warps).
// warp w: half = w&1 (16 ticks), egrp = w>>2-ish (w>>1) strides compacted list.
// thread lane owns sensors 2*lane, 2*lane+1 -> fully register-resident tile.
constexpr int SLICES  = 16;
constexpr int NSLICE  = N_EL / SLICES;   // 18750
constexpr int CHUNK   = 4096;
constexpr int LCAP    = 1024;
constexpr float GRAD  = 7.5f;            // gaussian radius: exp(-28.1) ~ 6e-13
constexpr float CNORM = 0.3989422804f;
constexpr float EM1   = 0.36787944117144233f;  // exp(-1)

__global__ __launch_bounds__(256)
void waveform_kernel(const float* __restrict__ zpos, float* __restrict__ out) {
    __shared__ float shZ[LCAP];
    __shared__ int   shIdx[LCAP];
    __shared__ int   s_cnt;

    const int tid  = threadIdx.x;
    const int lane = tid & 31;
    const int w    = tid >> 5;
    const int half = w & 1;
    const int eg   = w >> 1;                  // 0..3
    const int t0   = blockIdx.x * 32;
    const int tb   = t0 + half * 16;
    const int beg  = blockIdx.y * NSLICE;
    const int end  = min(N_EL, beg + NSLICE);
    const float zlo = (float)t0 - (GRAD + 0.6f);
    const float zhi = (float)(t0 + 31) + (GRAD + 0.6f);

    float acc0[16], acc1[16];
    #pragma unroll
    for (int i = 0; i < 16; i++) { acc0[i] = 0.f; acc1[i] = 0.f; }

    for (int base = beg; base < end; base += CHUNK) {
        if (tid == 0) s_cnt = 0;
        __syncthreads();
        #pragma unroll 4
        for (int k = 0; k < CHUNK / 256; k++) {
            int i = base + k * 256 + tid;
            if (i < end) {
                float zz = zpos[i];
                if (zz > zlo && zz < zhi) {
                    int p = atomicAdd(&s_cnt, 1);
                    if (p < LCAP) { shZ[p] = zz; shIdx[p] = i; }
                }
            }
        }
        __syncthreads();
        int ne = min(s_cnt, LCAP);
        for (int e = eg; e < ne; e += 4) {
            float zz = shZ[e];
            if (zz + GRAD < (float)tb || zz - GRAD > (float)(tb + 15)) continue;
            uint32 rr = g_R32[shIdx[e] * 32 + lane];
            __nv_bfloat162 rb = *reinterpret_cast<__nv_bfloat162*>(&rr);
            float r0 = __bfloat162float(rb.x), r1 = __bfloat162float(rb.y);
            float gg = 0.f, mm = 0.f;
            bool started = false;
            #pragma unroll
            for (int i = 0; i < 16; i++) {
                float d = (float)(tb + i) - zz;           // warp-uniform
                if (fabsf(d) <= GRAD) {
                    if (!started) {
                        gg = CNORM * __expf(-0.5f * d * d);
                        mm = __expf(-d - 0.5f);
                        started = true;
                    } else {
                        gg *= mm; mm *= EM1;
                    }
                    acc0[i] = fmaf(r0, gg, acc0[i]);
                    acc1[i] = fmaf(r1, gg, acc1[i]);
                }
            }
        }
        __syncthreads();
    }

    const int s0 = lane * 2;
    #pragma unroll
    for (int i = 0; i < 16; i++) {
        atomicAdd(&out[s0 * 1024 + tb + i], acc0[i]);
        atomicAdd(&out[(s0 + 1) * 1024 + tb + i], acc1[i]);
    }
}

// ---------------- launch ----------------
extern "C" void kernel_launch(void* const* d_in, const int* in_sizes, int n_in,
                              void* d_out, int out_size) {
    const float*  photons = (const float*)d_in[0];
    const float2* xy      = (const float2*)d_in[1];
    const float*  zpos    = (const float*)d_in[2];
    const float*  W1      = (const float*)d_in[3];
    const float*  b1      = (const float*)d_in[4];
    const float*  W2      = (const float*)d_in[5];
    const float*  b2      = (const float*)d_in[6];
    const float*  W3      = (const float*)d_in[7];
    const float*  b3      = (const float*)d_in[8];
    float* out = (float*)d_out;

    cudaFuncSetAttribute(mlp_kernel, cudaFuncAttributeMaxDynamicSharedMemorySize, SMEM_SZ);

    zero_kernel<<<SENS, 1024>>>(out);

    int mblocks = (N_EL + MROW - 1) / MROW;   // 1172
    mlp_kernel<<<mblocks, 512, SMEM_SZ>>>(photons, xy, W1, b1, W2, b2, W3, b3);

    dim3 wgrid(TICKS / 32, SLICES);
    waveform_kernel<<<wgrid, 256>>>(zpos, out);
}

// round 3
// speedup vs baseline: 1.1953x; 1.1953x over previous
#include <cuda_runtime.h>
#include <cuda_bf16.h>

typedef unsigned int uint32;

// ---------------- problem constants ----------------
constexpr int N_EL  = 300000;
constexpr int SENS  = 64;
constexpr int TICKS = 1024;
constexpr int HID   = 128;

// ---------------- scratch: response_of_sensors as bf16 [N, 64] ----------------
__device__ uint32 g_R32[(size_t)N_EL * (SENS / 2)];

// ---------------- helpers ----------------
__device__ __forceinline__ void mma16816(float* c, uint32 a0, uint32 a1, uint32 a2, uint32 a3,
                                         uint32 b0, uint32 b1) {
    asm volatile(
        "mma.sync.aligned.m16n8k16.row.col.f32.bf16.bf16.f32 "
        "{%0,%1,%2,%3},{%4,%5,%6,%7},{%8,%9},{%0,%1,%2,%3};\n"
        : "+f"(c[0]), "+f"(c[1]), "+f"(c[2]), "+f"(c[3])
        : "r"(a0), "r"(a1), "r"(a2), "r"(a3), "r"(b0), "r"(b1));
}

__device__ __forceinline__ uint32 packbf2(float a, float b) {
    __nv_bfloat162 t = __floats2bfloat162_rn(a, b);
    return *reinterpret_cast<uint32*>(&t);
}

// FFMA-only sigmoid: no MUFU. exp2 poly + bit-scale, reciprocal via Newton.
// |err| ~ 1e-6 rel over clamped range; clamp at |x|=15 (sigmoid tail < 3.1e-7).
__device__ __forceinline__ float fast_sigmoid(float x) {
    float y = fminf(fmaxf(x, -15.f), 15.f) * 1.44269504f;     // log2(e^x)
    float t = __fadd_rn(y, 12582912.f);                        // round-to-nearest int
    int   n = __float_as_int(t) - 0x4B400000;
    float f = y - __fsub_rn(t, 12582912.f);                    // f in [-0.5, 0.5]
    float p = 0.0013333558f;
    p = fmaf(p, f, 0.0096181291f);
    p = fmaf(p, f, 0.0555041087f);
    p = fmaf(p, f, 0.2402265070f);
    p = fmaf(p, f, 0.6931471806f);
    p = fmaf(p, f, 1.0f);
    float z = __int_as_float(__float_as_int(p) + (n << 23));   // z = e^x in [3e-7, 3.3e6]
    float a = 1.f + z;
    float r = __int_as_float(0x7EF311C3 - __float_as_int(a));  // ~rcp seed
    r = r * (2.f - a * r);
    r = r * (2.f - a * r);
    r = r * (2.f - a * r);
    return z * r;                                              // e^x / (1 + e^x)
}

// ======================= MLP kernel (register-resident, mma.sync) =======================
// 256 threads = 8 warps; each warp owns 16 electron rows per tile, fully independent.
// No h staging in smem: GEMM2 accumulator fragments repack directly into GEMM3 A fragments.
constexpr int KP  = 136;             // padded K stride (bf16 elems)
constexpr int NWT = N_EL / 16;       // 18750 warp-tiles (divides exactly)
constexpr int MLP_GRID = 296;        // 2 CTAs/SM persistent

constexpr int OFF_W2T = 0;                        // [128][KP] bf16 = 34816 B
constexpr int OFF_W3T = OFF_W2T + HID * KP * 2;   // [64][KP] bf16 = 17408 B
constexpr int OFF_W1  = OFF_W3T + SENS * KP * 2;  // float[256]
constexpr int OFF_B1  = OFF_W1 + 256 * 4;         // float[128]
constexpr int OFF_B2  = OFF_B1 + 128 * 4;         // float[128]
constexpr int OFF_B3  = OFF_B2 + 128 * 4;         // float[64]
constexpr int MLP_SMEM = OFF_B3 + 64 * 4;         // ~54.6 KB

__global__ __launch_bounds__(256, 2)
void mlp_kernel(const float* __restrict__ photons,
                const float2* __restrict__ xy,
                const float* __restrict__ W1, const float* __restrict__ b1,
                const float* __restrict__ W2, const float* __restrict__ b2,
                const float* __restrict__ W3, const float* __restrict__ b3) {
    extern __shared__ unsigned char sm[];
    __nv_bfloat16* sW2t = reinterpret_cast<__nv_bfloat16*>(sm + OFF_W2T);
    __nv_bfloat16* sW3t = reinterpret_cast<__nv_bfloat16*>(sm + OFF_W3T);
    float* sW1 = reinterpret_cast<float*>(sm + OFF_W1);
    float* sB1 = reinterpret_cast<float*>(sm + OFF_B1);
    float* sB2 = reinterpret_cast<float*>(sm + OFF_B2);
    float* sB3 = reinterpret_cast<float*>(sm + OFF_B3);

    const int tid = threadIdx.x;
    for (int i = tid; i < HID * HID; i += 256) {         // W2[k][n] -> sW2t[n][k]
        int k = i >> 7, n = i & 127;
        sW2t[n * KP + k] = __float2bfloat16_rn(W2[i]);
    }
    for (int i = tid; i < HID * SENS; i += 256) {        // W3[k][n] -> sW3t[n][k]
        int k = i >> 6, n = i & 63;
        sW3t[n * KP + k] = __float2bfloat16_rn(W3[i]);
    }
    for (int i = tid; i < 256; i += 256) sW1[i] = W1[i];
    if (tid < 128) { sB1[tid] = b1[tid]; sB2[tid] = b2[tid]; }
    if (tid < 64)  sB3[tid] = b3[tid];
    __syncthreads();

    const int wid  = tid >> 5, lane = tid & 31;
    const int g    = lane >> 2, tg = lane & 3;
    const int kq   = tg * 2;

    const int wslot   = blockIdx.x * 8 + wid;
    const int wstride = gridDim.x * 8;

    for (int wt = wslot; wt < NWT; wt += wstride) {
        const int r0 = wt * 16 + g, r1 = r0 + 8;
        const float2 p0 = xy[r0], p1 = xy[r1];
        const float ph0 = photons[r0], ph1 = photons[r1];

        // ---- GEMM2: acc = h1 @ W2^T, h1 A-fragments computed on the fly ----
        float acc[64];
        #pragma unroll
        for (int i = 0; i < 64; i++) acc[i] = 0.f;

        #pragma unroll
        for (int kt = 0; kt < 8; kt++) {
            const int kc = kt * 16 + kq;
            float w1a0 = sW1[kc],     w1b0 = sW1[128 + kc];
            float w1a1 = sW1[kc + 1], w1b1 = sW1[128 + kc + 1];
            float w1a2 = sW1[kc + 8], w1b2 = sW1[128 + kc + 8];
            float w1a3 = sW1[kc + 9], w1b3 = sW1[128 + kc + 9];
            float bb0 = sB1[kc], bb1 = sB1[kc + 1], bb2 = sB1[kc + 8], bb3 = sB1[kc + 9];
            float h00 = fmaxf(fmaf(p0.y, w1b0, fmaf(p0.x, w1a0, bb0)), 0.f);
            float h01 = fmaxf(fmaf(p0.y, w1b1, fmaf(p0.x, w1a1, bb1)), 0.f);
            float h10 = fmaxf(fmaf(p1.y, w1b0, fmaf(p1.x, w1a0, bb0)), 0.f);
            float h11 = fmaxf(fmaf(p1.y, w1b1, fmaf(p1.x, w1a1, bb1)), 0.f);
            float h02 = fmaxf(fmaf(p0.y, w1b2, fmaf(p0.x, w1a2, bb2)), 0.f);
            float h03 = fmaxf(fmaf(p0.y, w1b3, fmaf(p0.x, w1a3, bb3)), 0.f);
            float h12 = fmaxf(fmaf(p1.y, w1b2, fmaf(p1.x, w1a2, bb2)), 0.f);
            float h13 = fmaxf(fmaf(p1.y, w1b3, fmaf(p1.x, w1a3, bb3)), 0.f);
            uint32 a0 = packbf2(h00, h01), a1 = packbf2(h10, h11);
            uint32 a2 = packbf2(h02, h03), a3 = packbf2(h12, h13);
            #pragma unroll
            for (int nt = 0; nt < 16; nt++) {
                const __nv_bfloat16* Bp = sW2t + (nt * 8 + g) * KP + kc;
                uint32 b0 = *reinterpret_cast<const uint32*>(Bp);
                uint32 b1r = *reinterpret_cast<const uint32*>(Bp + 8);
                mma16816(&acc[nt * 4], a0, a1, a2, a3, b0, b1r);
            }
        }

        // ---- repack: h2 = relu(acc + b2) directly into GEMM3 A fragments ----
        uint32 A3[32];
        #pragma unroll
        for (int kt = 0; kt < 8; kt++) {
            const int nt0 = 2 * kt, nt1 = nt0 + 1;
            const int c0 = nt0 * 8 + kq, c1 = nt1 * 8 + kq;
            float b20 = sB2[c0], b21 = sB2[c0 + 1];
            float b22 = sB2[c1], b23 = sB2[c1 + 1];
            A3[kt * 4 + 0] = packbf2(fmaxf(acc[nt0 * 4 + 0] + b20, 0.f),
                                     fmaxf(acc[nt0 * 4 + 1] + b21, 0.f));
            A3[kt * 4 + 1] = packbf2(fmaxf(acc[nt0 * 4 + 2] + b20, 0.f),
                                     fmaxf(acc[nt0 * 4 + 3] + b21, 0.f));
            A3[kt * 4 + 2] = packbf2(fmaxf(acc[nt1 * 4 + 0] + b22, 0.f),
                                     fmaxf(acc[nt1 * 4 + 1] + b23, 0.f));
            A3[kt * 4 + 3] = packbf2(fmaxf(acc[nt1 * 4 + 2] + b22, 0.f),
                                     fmaxf(acc[nt1 * 4 + 3] + b23, 0.f));
        }

        // ---- GEMM3: acc3 = h2 @ W3^T ----
        float acc3[32];
        #pragma unroll
        for (int i = 0; i < 32; i++) acc3[i] = 0.f;
        #pragma unroll
        for (int kt = 0; kt < 8; kt++) {
            const int kc = kt * 16 + kq;
            #pragma unroll
            for (int nt = 0; nt < 8; nt++) {
                const __nv_bfloat16* Bp = sW3t + (nt * 8 + g) * KP + kc;
                uint32 b0 = *reinterpret_cast<const uint32*>(Bp);
                uint32 b1r = *reinterpret_cast<const uint32*>(Bp + 8);
                mma16816(&acc3[nt * 4], A3[kt * 4 + 0], A3[kt * 4 + 1],
                         A3[kt * 4 + 2], A3[kt * 4 + 3], b0, b1r);
            }
        }

        // ---- epilogue: r = photons * sigmoid(acc3 + b3) -> g_R32 (bf16x2) ----
        #pragma unroll
        for (int nt = 0; nt < 8; nt++) {
            const int c0 = nt * 8 + kq;
            float bb0 = sB3[c0], bb1 = sB3[c0 + 1];
            float s0 = fast_sigmoid(acc3[nt * 4 + 0] + bb0);
            float s1 = fast_sigmoid(acc3[nt * 4 + 1] + bb1);
            float s2 = fast_sigmoid(acc3[nt * 4 + 2] + bb0);
            float s3 = fast_sigmoid(acc3[nt * 4 + 3] + bb1);
            g_R32[(size_t)r0 * 32 + nt * 4 + tg] = packbf2(ph0 * s0, ph0 * s1);
            g_R32[(size_t)r1 * 32 + nt * 4 + tg] = packbf2(ph1 * s2, ph1 * s3);
        }
    }
}

// ---------------- output zeroing ----------------
__global__ void zero_kernel(float* __restrict__ out) {
    out[blockIdx.x * 1024 + threadIdx.x] = 0.f;
}

// ---------------- waveform scatter kernel (unchanged from R1 pass) ----------------
constexpr int SLICES  = 16;
constexpr int NSLICE  = N_EL / SLICES;   // 18750
constexpr int CHUNK   = 4096;
constexpr int LCAP    = 1024;
constexpr float GRAD  = 7.5f;
constexpr float CNORM = 0.3989422804f;
constexpr float EM1   = 0.36787944117144233f;

__global__ __launch_bounds__(256)
void waveform_kernel(const float* __restrict__ zpos, float* __restrict__ out) {
    __shared__ float shZ[LCAP];
    __shared__ int   shIdx[LCAP];
    __shared__ int   s_cnt;

    const int tid  = threadIdx.x;
    const int lane = tid & 31;
    const int w    = tid >> 5;
    const int half = w & 1;
    const int eg   = w >> 1;
    const int t0   = blockIdx.x * 32;
    const int tb   = t0 + half * 16;
    const int beg  = blockIdx.y * NSLICE;
    const int end  = min(N_EL, beg + NSLICE);
    const float zlo = (float)t0 - (GRAD + 0.6f);
    const float zhi = (float)(t0 + 31) + (GRAD + 0.6f);

    float acc0[16], acc1[16];
    #pragma unroll
    for (int i = 0; i < 16; i++) { acc0[i] = 0.f; acc1[i] = 0.f; }

    for (int base = beg; base < end; base += CHUNK) {
        if (tid == 0) s_cnt = 0;
        __syncthreads();
        #pragma unroll 4
        for (int k = 0; k < CHUNK / 256; k++) {
            int i = base + k * 256 + tid;
            if (i < end) {
                float zz = zpos[i];
                if (zz > zlo && zz < zhi) {
                    int p = atomicAdd(&s_cnt, 1);
                    if (p < LCAP) { shZ[p] = zz; shIdx[p] = i; }
                }
            }
        }
        __syncthreads();
        int ne = min(s_cnt, LCAP);
        for (int e = eg; e < ne; e += 4) {
            float zz = shZ[e];
            if (zz + GRAD < (float)tb || zz - GRAD > (float)(tb + 15)) continue;
            uint32 rrv = g_R32[(size_t)shIdx[e] * 32 + lane];
            __nv_bfloat162 rb = *reinterpret_cast<__nv_bfloat162*>(&rrv);
            float r0 = __bfloat162float(rb.x), r1 = __bfloat162float(rb.y);
            float gg = 0.f, mm = 0.f;
            bool started = false;
            #pragma unroll
            for (int i = 0; i < 16; i++) {
                float d = (float)(tb + i) - zz;
                if (fabsf(d) <= GRAD) {
                    if (!started) {
                        gg = CNORM * __expf(-0.5f * d * d);
                        mm = __expf(-d - 0.5f);
                        started = true;
                    } else {
                        gg *= mm; mm *= EM1;
                    }
                    acc0[i] = fmaf(r0, gg, acc0[i]);
                    acc1[i] = fmaf(r1, gg, acc1[i]);
                }
            }
        }
        __syncthreads();
    }

    const int s0 = lane * 2;
    #pragma unroll
    for (int i = 0; i < 16; i++) {
        atomicAdd(&out[s0 * 1024 + tb + i], acc0[i]);
        atomicAdd(&out[(s0 + 1) * 1024 + tb + i], acc1[i]);
    }
}

// ---------------- launch ----------------
extern "C" void kernel_launch(void* const* d_in, const int* in_sizes, int n_in,
                              void* d_out, int out_size) {
    const float*  photons = (const float*)d_in[0];
    const float2* xy      = (const float2*)d_in[1];
    const float*  zpos    = (const float*)d_in[2];
    const float*  W1      = (const float*)d_in[3];
    const float*  b1      = (const float*)d_in[4];
    const float*  W2      = (const float*)d_in[5];
    const float*  b2      = (const float*)d_in[6];
    const float*  W3      = (const float*)d_in[7];
    const float*  b3      = (const float*)d_in[8];
    float* out = (float*)d_out;

    cudaFuncSetAttribute(mlp_kernel, cudaFuncAttributeMaxDynamicSharedMemorySize, MLP_SMEM);

    // mlp first (position 0 -> lands under the ncu capture window), zero before waveform.
    mlp_kernel<<<MLP_GRID, 256, MLP_SMEM>>>(photons, xy, W1, b1, W2, b2, W3, b3);
    zero_kernel<<<SENS, 1024>>>(out);

    dim3 wgrid(TICKS / 32, SLICES);
    waveform_kernel<<<wgrid, 256>>>(zpos, out);
}

// round 4
// speedup vs baseline: 2.7332x; 2.2866x over previous
#include <cuda_runtime.h>
#include <cuda_bf16.h>

typedef unsigned int uint32;
typedef unsigned short u16;

// ---------------- problem constants ----------------
constexpr int N_EL  = 300000;
constexpr int SENS  = 64;
constexpr int TICKS = 1024;
constexpr int HID   = 128;

// ---------------- scratch: response_of_sensors as bf16 [N, 64] ----------------
__device__ uint32 g_R32[(size_t)N_EL * (SENS / 2)];

// ---------------- helpers ----------------
__device__ __forceinline__ void mma16816(float* c, uint32 a0, uint32 a1, uint32 a2, uint32 a3,
                                         uint32 b0, uint32 b1) {
    asm volatile(
        "mma.sync.aligned.m16n8k16.row.col.f32.bf16.bf16.f32 "
        "{%0,%1,%2,%3},{%4,%5,%6,%7},{%8,%9},{%0,%1,%2,%3};\n"
        : "+f"(c[0]), "+f"(c[1]), "+f"(c[2]), "+f"(c[3])
        : "r"(a0), "r"(a1), "r"(a2), "r"(a3), "r"(b0), "r"(b1));
}

__device__ __forceinline__ uint32 packbf2(float a, float b) {
    __nv_bfloat162 t = __floats2bfloat162_rn(a, b);
    return *reinterpret_cast<uint32*>(&t);
}

// FFMA-only sigmoid (no MUFU): exp2 poly + bit-scale, rcp via Newton.
__device__ __forceinline__ float fast_sigmoid(float x) {
    float y = fminf(fmaxf(x, -15.f), 15.f) * 1.44269504f;
    float t = __fadd_rn(y, 12582912.f);
    int   n = __float_as_int(t) - 0x4B400000;
    float f = y - __fsub_rn(t, 12582912.f);
    float p = 0.0013333558f;
    p = fmaf(p, f, 0.0096181291f);
    p = fmaf(p, f, 0.0555041087f);
    p = fmaf(p, f, 0.2402265070f);
    p = fmaf(p, f, 0.6931471806f);
    p = fmaf(p, f, 1.0f);
    float z = __int_as_float(__float_as_int(p) + (n << 23));
    float a = 1.f + z;
    float r = __int_as_float(0x7EF311C3 - __float_as_int(a));
    r = r * (2.f - a * r);
    r = r * (2.f - a * r);
    r = r * (2.f - a * r);
    return z * r;
}

// ======================= MLP kernel (unchanged from R3 pass) =======================
constexpr int KP  = 136;
constexpr int NWT = N_EL / 16;
constexpr int MLP_GRID = 296;

constexpr int OFF_W2T = 0;
constexpr int OFF_W3T = OFF_W2T + HID * KP * 2;
constexpr int OFF_W1  = OFF_W3T + SENS * KP * 2;
constexpr int OFF_B1  = OFF_W1 + 256 * 4;
constexpr int OFF_B2  = OFF_B1 + 128 * 4;
constexpr int OFF_B3  = OFF_B2 + 128 * 4;
constexpr int MLP_SMEM = OFF_B3 + 64 * 4;

__global__ __launch_bounds__(256, 2)
void mlp_kernel(const float* __restrict__ photons,
                const float2* __restrict__ xy,
                const float* __restrict__ W1, const float* __restrict__ b1,
                const float* __restrict__ W2, const float* __restrict__ b2,
                const float* __restrict__ W3, const float* __restrict__ b3) {
    extern __shared__ unsigned char sm[];
    __nv_bfloat16* sW2t = reinterpret_cast<__nv_bfloat16*>(sm + OFF_W2T);
    __nv_bfloat16* sW3t = reinterpret_cast<__nv_bfloat16*>(sm + OFF_W3T);
    float* sW1 = reinterpret_cast<float*>(sm + OFF_W1);
    float* sB1 = reinterpret_cast<float*>(sm + OFF_B1);
    float* sB2 = reinterpret_cast<float*>(sm + OFF_B2);
    float* sB3 = reinterpret_cast<float*>(sm + OFF_B3);

    const int tid = threadIdx.x;
    for (int i = tid; i < HID * HID; i += 256) {
        int k = i >> 7, n = i & 127;
        sW2t[n * KP + k] = __float2bfloat16_rn(W2[i]);
    }
    for (int i = tid; i < HID * SENS; i += 256) {
        int k = i >> 6, n = i & 63;
        sW3t[n * KP + k] = __float2bfloat16_rn(W3[i]);
    }
    for (int i = tid; i < 256; i += 256) sW1[i] = W1[i];
    if (tid < 128) { sB1[tid] = b1[tid]; sB2[tid] = b2[tid]; }
    if (tid < 64)  sB3[tid] = b3[tid];
    __syncthreads();

    const int wid  = tid >> 5, lane = tid & 31;
    const int g    = lane >> 2, tg = lane & 3;
    const int kq   = tg * 2;

    const int wslot   = blockIdx.x * 8 + wid;
    const int wstride = gridDim.x * 8;

    for (int wt = wslot; wt < NWT; wt += wstride) {
        const int r0 = wt * 16 + g, r1 = r0 + 8;
        const float2 p0 = xy[r0], p1 = xy[r1];
        const float ph0 = photons[r0], ph1 = photons[r1];

        float acc[64];
        #pragma unroll
        for (int i = 0; i < 64; i++) acc[i] = 0.f;

        #pragma unroll
        for (int kt = 0; kt < 8; kt++) {
            const int kc = kt * 16 + kq;
            float w1a0 = sW1[kc],     w1b0 = sW1[128 + kc];
            float w1a1 = sW1[kc + 1], w1b1 = sW1[128 + kc + 1];
            float w1a2 = sW1[kc + 8], w1b2 = sW1[128 + kc + 8];
            float w1a3 = sW1[kc + 9], w1b3 = sW1[128 + kc + 9];
            float bb0 = sB1[kc], bb1 = sB1[kc + 1], bb2 = sB1[kc + 8], bb3 = sB1[kc + 9];
            float h00 = fmaxf(fmaf(p0.y, w1b0, fmaf(p0.x, w1a0, bb0)), 0.f);
            float h01 = fmaxf(fmaf(p0.y, w1b1, fmaf(p0.x, w1a1, bb1)), 0.f);
            float h10 = fmaxf(fmaf(p1.y, w1b0, fmaf(p1.x, w1a0, bb0)), 0.f);
            float h11 = fmaxf(fmaf(p1.y, w1b1, fmaf(p1.x, w1a1, bb1)), 0.f);
            float h02 = fmaxf(fmaf(p0.y, w1b2, fmaf(p0.x, w1a2, bb2)), 0.f);
            float h03 = fmaxf(fmaf(p0.y, w1b3, fmaf(p0.x, w1a3, bb3)), 0.f);
            float h12 = fmaxf(fmaf(p1.y, w1b2, fmaf(p1.x, w1a2, bb2)), 0.f);
            float h13 = fmaxf(fmaf(p1.y, w1b3, fmaf(p1.x, w1a3, bb3)), 0.f);
            uint32 a0 = packbf2(h00, h01), a1 = packbf2(h10, h11);
            uint32 a2 = packbf2(h02, h03), a3 = packbf2(h12, h13);
            #pragma unroll
            for (int nt = 0; nt < 16; nt++) {
                const __nv_bfloat16* Bp = sW2t + (nt * 8 + g) * KP + kc;
                uint32 b0 = *reinterpret_cast<const uint32*>(Bp);
                uint32 b1r = *reinterpret_cast<const uint32*>(Bp + 8);
                mma16816(&acc[nt * 4], a0, a1, a2, a3, b0, b1r);
            }
        }

        uint32 A3[32];
        #pragma unroll
        for (int kt = 0; kt < 8; kt++) {
            const int nt0 = 2 * kt, nt1 = nt0 + 1;
            const int c0 = nt0 * 8 + kq, c1 = nt1 * 8 + kq;
            float b20 = sB2[c0], b21 = sB2[c0 + 1];
            float b22 = sB2[c1], b23 = sB2[c1 + 1];
            A3[kt * 4 + 0] = packbf2(fmaxf(acc[nt0 * 4 + 0] + b20, 0.f),
                                     fmaxf(acc[nt0 * 4 + 1] + b21, 0.f));
            A3[kt * 4 + 1] = packbf2(fmaxf(acc[nt0 * 4 + 2] + b20, 0.f),
                                     fmaxf(acc[nt0 * 4 + 3] + b21, 0.f));
            A3[kt * 4 + 2] = packbf2(fmaxf(acc[nt1 * 4 + 0] + b22, 0.f),
                                     fmaxf(acc[nt1 * 4 + 1] + b23, 0.f));
            A3[kt * 4 + 3] = packbf2(fmaxf(acc[nt1 * 4 + 2] + b22, 0.f),
                                     fmaxf(acc[nt1 * 4 + 3] + b23, 0.f));
        }

        float acc3[32];
        #pragma unroll
        for (int i = 0; i < 32; i++) acc3[i] = 0.f;
        #pragma unroll
        for (int kt = 0; kt < 8; kt++) {
            const int kc = kt * 16 + kq;
            #pragma unroll
            for (int nt = 0; nt < 8; nt++) {
                const __nv_bfloat16* Bp = sW3t + (nt * 8 + g) * KP + kc;
                uint32 b0 = *reinterpret_cast<const uint32*>(Bp);
                uint32 b1r = *reinterpret_cast<const uint32*>(Bp + 8);
                mma16816(&acc3[nt * 4], A3[kt * 4 + 0], A3[kt * 4 + 1],
                         A3[kt * 4 + 2], A3[kt * 4 + 3], b0, b1r);
            }
        }

        #pragma unroll
        for (int nt = 0; nt < 8; nt++) {
            const int c0 = nt * 8 + kq;
            float bb0 = sB3[c0], bb1 = sB3[c0 + 1];
            float s0 = fast_sigmoid(acc3[nt * 4 + 0] + bb0);
            float s1 = fast_sigmoid(acc3[nt * 4 + 1] + bb1);
            float s2 = fast_sigmoid(acc3[nt * 4 + 2] + bb0);
            float s3 = fast_sigmoid(acc3[nt * 4 + 3] + bb1);
            g_R32[(size_t)r0 * 32 + nt * 4 + tg] = packbf2(ph0 * s0, ph0 * s1);
            g_R32[(size_t)r1 * 32 + nt * 4 + tg] = packbf2(ph1 * s2, ph1 * s3);
        }
    }
}

// ---------------- output zeroing ----------------
__global__ void zero_kernel(float* __restrict__ out) {
    out[blockIdx.x * 1024 + threadIdx.x] = 0.f;
}

// ======================= waveform kernel: banded GEMM =======================
// Grid (32 tick-tiles, 12 electron slices). Block 256 threads = 8 warps.
// Per tile: compact in-range electrons; per 256-electron chunk: build E^T
// [32 ticks][256] bf16 via lane-parallel log-recurrence, stage R^T [64][256]
// bf16, then C[64x32] += R^T @ E via mma (8 warps = 4 m-tiles x 2 n-halves).
constexpr int WV_NSL   = 12;
constexpr int WV_SLICE = N_EL / WV_NSL;    // 25000
constexpr int WV_CAP   = 2048;
constexpr int WV_R     = 5;                // inclusion radius (ticks)
constexpr float CNORM  = 0.3989422804f;
constexpr float EM1    = 0.36787944117144233f;

constexpr int EST_S = 264;   // E_sT row stride (u16 elems): conflict-free frag loads
constexpr int RST_S = 266;   // R_sT row stride (u16 elems): deg<=2 both paths

constexpr int WOFF_SZ  = 0;                        // float[2048]
constexpr int WOFF_IDX = WOFF_SZ + WV_CAP * 4;     // int[2048]
constexpr int WOFF_EST = WOFF_IDX + WV_CAP * 4;    // u16[32*264]   = 16896 B
constexpr int WOFF_RST = WOFF_EST + 32 * EST_S * 2;// u16[64*266]   = 34048 B
constexpr int WOFF_CNT = WOFF_RST + 64 * RST_S * 2;
constexpr int WV_SMEM  = WOFF_CNT + 16;            // ~67.4 KB

__global__ __launch_bounds__(256, 1)
void waveform_gemm(const float* __restrict__ zpos, float* __restrict__ out) {
    extern __shared__ unsigned char sm[];
    float* sZ   = reinterpret_cast<float*>(sm + WOFF_SZ);
    int*   sIdx = reinterpret_cast<int*>(sm + WOFF_IDX);
    u16*   EST  = reinterpret_cast<u16*>(sm + WOFF_EST);
    u16*   RST  = reinterpret_cast<u16*>(sm + WOFF_RST);
    int*   sCnt = reinterpret_cast<int*>(sm + WOFF_CNT);

    const int tid  = threadIdx.x;
    const int lane = tid & 31;
    const int wid  = tid >> 5;
    const int g    = lane >> 2, tg = lane & 3;
    const int t0   = blockIdx.x * 32;
    const int beg  = blockIdx.y * WV_SLICE;
    const int end  = beg + WV_SLICE;

    // ---- compaction: electrons with round(z) in [t0-R, t0+31+R] ----
    if (tid == 0) *sCnt = 0;
    __syncthreads();
    for (int i = beg + tid; i < end; i += 256) {
        float zz = zpos[i];
        int c = __float2int_rn(zz);
        if (c >= t0 - WV_R && c <= t0 + 31 + WV_R) {
            int p = atomicAdd(sCnt, 1);
            if (p < WV_CAP) { sZ[p] = zz; sIdx[p] = i; }
        }
    }
    __syncthreads();
    const int ne = min(*sCnt, WV_CAP);

    float C[8];
    #pragma unroll
    for (int i = 0; i < 8; i++) C[i] = 0.f;

    const int mt = wid & 3;       // m-tile (16 sensors)
    const int nh = wid >> 2;      // n-half (16 ticks)

    for (int cb = 0; cb < ne; cb += 256) {
        // ---- build E^T: each thread = one electron, 32 ticks, branchless ----
        {
            const int e = cb + tid;
            const bool valid = (e < ne);
            const float zz = valid ? sZ[e] : 0.f;
            const int   c  = __float2int_rn(zz);
            const int   js = min(max(c - WV_R - t0, 0), 31);
            const float ds = (float)(t0 + js) - zz;
            const float vm = valid ? 1.f : 0.f;
            const float gst = CNORM * __expf(-0.5f * ds * ds) * vm;
            const float mst = __expf(-ds - 0.5f) * vm;
            float gg = 0.f, mm = 0.f;
            #pragma unroll
            for (int j = 0; j < 32; j++) {
                bool fresh = (j == js);
                gg = fresh ? gst : gg * mm;
                mm = fresh ? mst : mm * EM1;
                EST[j * EST_S + tid] = __bfloat16_as_ushort(__float2bfloat16_rn(gg));
            }
        }
        // ---- stage R^T: warp loads 32 electron rows, pair-transpose via PRMT ----
        {
            #pragma unroll
            for (int r2 = 0; r2 < 16; r2++) {
                const int le0 = wid * 32 + 2 * r2;       // local col (even)
                const int e0 = cb + le0, e1 = e0 + 1;
                const int i0 = sIdx[min(e0, ne - 1)];
                const int i1 = sIdx[min(e1, ne - 1)];
                const uint32 v0 = g_R32[(size_t)i0 * 32 + lane];
                const uint32 v1 = g_R32[(size_t)i1 * 32 + lane];
                const uint32 lo = __byte_perm(v0, v1, 0x5410);
                const uint32 hi = __byte_perm(v0, v1, 0x7632);
                *reinterpret_cast<uint32*>(RST + (2 * lane) * RST_S + le0)     = lo;
                *reinterpret_cast<uint32*>(RST + (2 * lane + 1) * RST_S + le0) = hi;
            }
        }
        __syncthreads();

        // ---- GEMM: C[mt-tile][nh-half] += A-frags x B-frags over K=256 ----
        #pragma unroll
        for (int ks = 0; ks < 16; ks++) {
            const int kb = ks * 16 + 2 * tg;
            const u16* Ar0 = RST + (mt * 16 + g) * RST_S + kb;
            const u16* Ar1 = RST + (mt * 16 + g + 8) * RST_S + kb;
            uint32 a0 = *reinterpret_cast<const uint32*>(Ar0);
            uint32 a1 = *reinterpret_cast<const uint32*>(Ar1);
            uint32 a2 = *reinterpret_cast<const uint32*>(Ar0 + 8);
            uint32 a3 = *reinterpret_cast<const uint32*>(Ar1 + 8);
            #pragma unroll
            for (int nt = 0; nt < 2; nt++) {
                const u16* Bp = EST + ((nh * 2 + nt) * 8 + g) * EST_S + kb;
                uint32 b0 = *reinterpret_cast<const uint32*>(Bp);
                uint32 b1 = *reinterpret_cast<const uint32*>(Bp + 8);
                mma16816(&C[nt * 4], a0, a1, a2, a3, b0, b1);
            }
        }
        __syncthreads();
    }

    // ---- epilogue: scatter C fragments to out via atomics ----
    #pragma unroll
    for (int nt = 0; nt < 2; nt++) {
        const int tcol = t0 + (nh * 2 + nt) * 8 + 2 * tg;
        const int srow = mt * 16 + g;
        atomicAdd(&out[srow * 1024 + tcol],           C[nt * 4 + 0]);
        atomicAdd(&out[srow * 1024 + tcol + 1],       C[nt * 4 + 1]);
        atomicAdd(&out[(srow + 8) * 1024 + tcol],     C[nt * 4 + 2]);
        atomicAdd(&out[(srow + 8) * 1024 + tcol + 1], C[nt * 4 + 3]);
    }
}

// ---------------- launch ----------------
extern "C" void kernel_launch(void* const* d_in, const int* in_sizes, int n_in,
                              void* d_out, int out_size) {
    const float*  photons = (const float*)d_in[0];
    const float2* xy      = (const float2*)d_in[1];
    const float*  zpos    = (const float*)d_in[2];
    const float*  W1      = (const float*)d_in[3];
    const float*  b1      = (const float*)d_in[4];
    const float*  W2      = (const float*)d_in[5];
    const float*  b2      = (const float*)d_in[6];
    const float*  W3      = (const float*)d_in[7];
    const float*  b3      = (const float*)d_in[8];
    float* out = (float*)d_out;

    cudaFuncSetAttribute(mlp_kernel, cudaFuncAttributeMaxDynamicSharedMemorySize, MLP_SMEM);
    cudaFuncSetAttribute(waveform_gemm, cudaFuncAttributeMaxDynamicSharedMemorySize, WV_SMEM);

    mlp_kernel<<<MLP_GRID, 256, MLP_SMEM>>>(photons, xy, W1, b1, W2, b2, W3, b3);
    zero_kernel<<<SENS, 1024>>>(out);

    dim3 wgrid(TICKS / 32, WV_NSL);
    waveform_gemm<<<wgrid, 256, WV_SMEM>>>(zpos, out);
}

// round 5
// speedup vs baseline: 3.4589x; 1.2655x over previous
#include <cuda_runtime.h>
#include <cuda_bf16.h>

typedef unsigned int uint32;
typedef unsigned short u16;

// ---------------- problem constants ----------------
constexpr int N_EL  = 300000;
constexpr int SENS  = 64;
constexpr int TICKS = 1024;
constexpr int HID   = 128;

// ---------------- global scratch ----------------
__device__ uint32 g_R32[(size_t)N_EL * (SENS / 2)];   // response bf16x2 [N][32]

constexpr int NBIN = 32;       // 32-tick tiles
constexpr int BCAP = 16384;
constexpr int WV_R = 5;        // gaussian inclusion radius (ticks)
__device__ float g_binZ[NBIN * BCAP];
__device__ int   g_binI[NBIN * BCAP];
__device__ int   g_binCnt[NBIN];

// ---------------- helpers ----------------
__device__ __forceinline__ void mma16816(float* c, uint32 a0, uint32 a1, uint32 a2, uint32 a3,
                                         uint32 b0, uint32 b1) {
    asm volatile(
        "mma.sync.aligned.m16n8k16.row.col.f32.bf16.bf16.f32 "
        "{%0,%1,%2,%3},{%4,%5,%6,%7},{%8,%9},{%0,%1,%2,%3};\n"
        : "+f"(c[0]), "+f"(c[1]), "+f"(c[2]), "+f"(c[3])
        : "r"(a0), "r"(a1), "r"(a2), "r"(a3), "r"(b0), "r"(b1));
}

__device__ __forceinline__ void ldsm4(uint32& r0, uint32& r1, uint32& r2, uint32& r3,
                                      uint32 addr) {
    asm volatile("ldmatrix.sync.aligned.m8n8.x4.shared.b16 {%0,%1,%2,%3}, [%4];"
        : "=r"(r0), "=r"(r1), "=r"(r2), "=r"(r3) : "r"(addr));
}

__device__ __forceinline__ uint32 smem_u32(const void* p) {
    uint32 a;
    asm("{ .reg .u64 t; cvta.to.shared.u64 t, %1; cvt.u32.u64 %0, t; }" : "=r"(a) : "l"(p));
    return a;
}

__device__ __forceinline__ uint32 packbf2(float a, float b) {
    __nv_bfloat162 t = __floats2bfloat162_rn(a, b);
    return *reinterpret_cast<uint32*>(&t);
}

// FFMA-only sigmoid (no MUFU), 2 Newton steps (rel err ~1e-6)
__device__ __forceinline__ float fast_sigmoid(float x) {
    float y = fminf(fmaxf(x, -15.f), 15.f) * 1.44269504f;
    float t = __fadd_rn(y, 12582912.f);
    int   n = __float_as_int(t) - 0x4B400000;
    float f = y - __fsub_rn(t, 12582912.f);
    float p = 0.0013333558f;
    p = fmaf(p, f, 0.0096181291f);
    p = fmaf(p, f, 0.0555041087f);
    p = fmaf(p, f, 0.2402265070f);
    p = fmaf(p, f, 0.6931471806f);
    p = fmaf(p, f, 1.0f);
    float z = __int_as_float(__float_as_int(p) + (n << 23));
    float a = 1.f + z;
    float r = __int_as_float(0x7EF311C3 - __float_as_int(a));
    r = r * (2.f - a * r);
    r = r * (2.f - a * r);
    return z * r;
}

// ======================= MLP kernel =======================
// 256 threads = 8 warps, warp owns 16 electron rows per tile.
// Layer1 done as mma with A=[x,y,1] (K=16 padded), B=[W1^T | b1 | 0].
// B fragments for GEMM2/GEMM3 via ldmatrix.x4 (KP=136 -> conflict-free).
constexpr int KP  = 136;
constexpr int NWT = N_EL / 16;       // 18750
constexpr int MLP_GRID = 296;

constexpr int OFF_W2T = 0;                          // [128][KP] bf16 = 34816 B
constexpr int OFF_W3T = OFF_W2T + HID * KP * 2;     // [64][KP]  bf16 = 17408 B
constexpr int OFF_W1E = OFF_W3T + SENS * KP * 2;    // [128][16] bf16 = 4096 B
constexpr int OFF_B2  = OFF_W1E + 128 * 16 * 2;     // float[128]
constexpr int OFF_B3  = OFF_B2 + 128 * 4;           // float[64]
constexpr int MLP_SMEM = OFF_B3 + 64 * 4;           // ~57 KB

__global__ __launch_bounds__(256, 2)
void mlp_kernel(const float* __restrict__ photons,
                const float2* __restrict__ xy,
                const float* __restrict__ W1, const float* __restrict__ b1,
                const float* __restrict__ W2, const float* __restrict__ b2,
                const float* __restrict__ W3, const float* __restrict__ b3) {
    extern __shared__ unsigned char sm[];
    __nv_bfloat16* sW2t = reinterpret_cast<__nv_bfloat16*>(sm + OFF_W2T);
    __nv_bfloat16* sW3t = reinterpret_cast<__nv_bfloat16*>(sm + OFF_W3T);
    __nv_bfloat16* sW1e = reinterpret_cast<__nv_bfloat16*>(sm + OFF_W1E);
    float* sB2 = reinterpret_cast<float*>(sm + OFF_B2);
    float* sB3 = reinterpret_cast<float*>(sm + OFF_B3);

    const int tid = threadIdx.x;
    for (int i = tid; i < HID * HID; i += 256) {         // W2[k][n] -> sW2t[n][k]
        int k = i >> 7, n = i & 127;
        sW2t[n * KP + k] = __float2bfloat16_rn(W2[i]);
    }
    for (int i = tid; i < HID * SENS; i += 256) {        // W3[k][n] -> sW3t[n][k]
        int k = i >> 6, n = i & 63;
        sW3t[n * KP + k] = __float2bfloat16_rn(W3[i]);
    }
    for (int i = tid; i < 128 * 16; i += 256) {          // W1ext[n][k]
        int n = i >> 4, k = i & 15;
        float v = (k == 0) ? W1[n] : (k == 1) ? W1[128 + n] : (k == 2) ? b1[n] : 0.f;
        sW1e[i] = __float2bfloat16_rn(v);
    }
    if (tid < 128) sB2[tid] = b2[tid];
    if (tid < 64)  sB3[tid] = b3[tid];
    __syncthreads();

    const int wid = tid >> 5, lane = tid & 31;
    const int g = lane >> 2, tg = lane & 3;
    const int kq = tg * 2;

    // ldmatrix per-lane base offsets (bytes) within a [rows][KP] bf16 panel
    const int row_in = (lane & 7) + ((lane >> 4) << 3);
    const int k8off  = (lane >> 3) & 1;
    const uint32 lmB2 = smem_u32(sW2t) + (uint32)(row_in * (KP * 2) + k8off * 16);
    const uint32 lmB3 = smem_u32(sW3t) + (uint32)(row_in * (KP * 2) + k8off * 16);

    const int wslot   = blockIdx.x * 8 + wid;
    const int wstride = gridDim.x * 8;

    for (int wt = wslot; wt < NWT; wt += wstride) {
        const int r0 = wt * 16 + g, r1 = r0 + 8;
        const float2 p0 = xy[r0], p1 = xy[r1];
        const float ph0 = photons[r0], ph1 = photons[r1];

        // ---- GEMM1: h1 = relu([x,y,1] @ W1ext), M=16 N=128 K=16 ----
        float acc1[64];
        #pragma unroll
        for (int i = 0; i < 64; i++) acc1[i] = 0.f;
        const uint32 xa0 = (tg == 0) ? packbf2(p0.x, p0.y) : ((tg == 1) ? 0x00003F80u : 0u);
        const uint32 xa1 = (tg == 0) ? packbf2(p1.x, p1.y) : ((tg == 1) ? 0x00003F80u : 0u);
        #pragma unroll
        for (int nt = 0; nt < 16; nt++) {
            uint32 b0 = *reinterpret_cast<const uint32*>(sW1e + (nt * 8 + g) * 16 + kq);
            mma16816(&acc1[nt * 4], xa0, xa1, 0u, 0u, b0, 0u);
        }

        // ---- repack h1 -> GEMM2 A fragments (relu; bias already in GEMM1) ----
        uint32 A2[32];
        #pragma unroll
        for (int kt = 0; kt < 8; kt++) {
            A2[kt * 4 + 0] = packbf2(fmaxf(acc1[8 * kt + 0], 0.f), fmaxf(acc1[8 * kt + 1], 0.f));
            A2[kt * 4 + 1] = packbf2(fmaxf(acc1[8 * kt + 2], 0.f), fmaxf(acc1[8 * kt + 3], 0.f));
            A2[kt * 4 + 2] = packbf2(fmaxf(acc1[8 * kt + 4], 0.f), fmaxf(acc1[8 * kt + 5], 0.f));
            A2[kt * 4 + 3] = packbf2(fmaxf(acc1[8 * kt + 6], 0.f), fmaxf(acc1[8 * kt + 7], 0.f));
        }

        // ---- GEMM2: acc2 = h1 @ W2^T (B frags via ldmatrix.x4) ----
        float acc2[64];
        #pragma unroll
        for (int i = 0; i < 64; i++) acc2[i] = 0.f;
        #pragma unroll
        for (int kt = 0; kt < 8; kt++) {
            #pragma unroll
            for (int p = 0; p < 8; p++) {
                uint32 b0, b1r, b2r, b3r;
                ldsm4(b0, b1r, b2r, b3r, lmB2 + (uint32)(p * 16 * (KP * 2) + kt * 32));
                mma16816(&acc2[(2 * p) * 4], A2[kt * 4 + 0], A2[kt * 4 + 1],
                         A2[kt * 4 + 2], A2[kt * 4 + 3], b0, b1r);
                mma16816(&acc2[(2 * p + 1) * 4], A2[kt * 4 + 0], A2[kt * 4 + 1],
                         A2[kt * 4 + 2], A2[kt * 4 + 3], b2r, b3r);
            }
        }

        // ---- repack: h2 = relu(acc2 + b2) -> GEMM3 A fragments ----
        uint32 A3[32];
        #pragma unroll
        for (int kt = 0; kt < 8; kt++) {
            const int nt0 = 2 * kt, nt1 = nt0 + 1;
            const int c0 = nt0 * 8 + kq, c1 = nt1 * 8 + kq;
            float b20 = sB2[c0], b21 = sB2[c0 + 1];
            float b22 = sB2[c1], b23 = sB2[c1 + 1];
            A3[kt * 4 + 0] = packbf2(fmaxf(acc2[nt0 * 4 + 0] + b20, 0.f),
                                     fmaxf(acc2[nt0 * 4 + 1] + b21, 0.f));
            A3[kt * 4 + 1] = packbf2(fmaxf(acc2[nt0 * 4 + 2] + b20, 0.f),
                                     fmaxf(acc2[nt0 * 4 + 3] + b21, 0.f));
            A3[kt * 4 + 2] = packbf2(fmaxf(acc2[nt1 * 4 + 0] + b22, 0.f),
                                     fmaxf(acc2[nt1 * 4 + 1] + b23, 0.f));
            A3[kt * 4 + 3] = packbf2(fmaxf(acc2[nt1 * 4 + 2] + b22, 0.f),
                                     fmaxf(acc2[nt1 * 4 + 3] + b23, 0.f));
        }

        // ---- GEMM3: acc3 = h2 @ W3^T ----
        float acc3[32];
        #pragma unroll
        for (int i = 0; i < 32; i++) acc3[i] = 0.f;
        #pragma unroll
        for (int kt = 0; kt < 8; kt++) {
            #pragma unroll
            for (int p = 0; p < 4; p++) {
                uint32 b0, b1r, b2r, b3r;
                ldsm4(b0, b1r, b2r, b3r, lmB3 + (uint32)(p * 16 * (KP * 2) + kt * 32));
                mma16816(&acc3[(2 * p) * 4], A3[kt * 4 + 0], A3[kt * 4 + 1],
                         A3[kt * 4 + 2], A3[kt * 4 + 3], b0, b1r);
                mma16816(&acc3[(2 * p + 1) * 4], A3[kt * 4 + 0], A3[kt * 4 + 1],
                         A3[kt * 4 + 2], A3[kt * 4 + 3], b2r, b3r);
            }
        }

        // ---- epilogue: r = photons * sigmoid(acc3 + b3) ----
        #pragma unroll
        for (int nt = 0; nt < 8; nt++) {
            const int c0 = nt * 8 + kq;
            float bb0 = sB3[c0], bb1 = sB3[c0 + 1];
            float s0 = fast_sigmoid(acc3[nt * 4 + 0] + bb0);
            float s1 = fast_sigmoid(acc3[nt * 4 + 1] + bb1);
            float s2 = fast_sigmoid(acc3[nt * 4 + 2] + bb0);
            float s3 = fast_sigmoid(acc3[nt * 4 + 3] + bb1);
            g_R32[(size_t)r0 * 32 + nt * 4 + tg] = packbf2(ph0 * s0, ph0 * s1);
            g_R32[(size_t)r1 * 32 + nt * 4 + tg] = packbf2(ph1 * s2, ph1 * s3);
        }
    }
}

// ---------------- output zeroing + bin-count reset ----------------
__global__ void zero_kernel(float* __restrict__ out) {
    int i = blockIdx.x * 1024 + threadIdx.x;
    out[i] = 0.f;
    if (i < NBIN) g_binCnt[i] = 0;
}

// ---------------- binning kernel: scatter (z, idx) into per-tile lists ----------------
__global__ __launch_bounds__(256)
void bin_kernel(const float* __restrict__ zpos) {
    __shared__ int hist[NBIN], sbase[NBIN];
    const int tid = threadIdx.x;
    if (tid < NBIN) hist[tid] = 0;
    __syncthreads();

    const int i = blockIdx.x * 256 + tid;
    float zz = 0.f;
    int t0i = -1, t1i = -1, s0 = 0, s1 = 0;
    if (i < N_EL) {
        zz = zpos[i];
        int c = __float2int_rn(zz);
        int lo = max(c - WV_R, 0) >> 5;
        int hi = min(c + WV_R, TICKS - 1) >> 5;
        t0i = lo; s0 = atomicAdd(&hist[lo], 1);
        if (hi != lo) { t1i = hi; s1 = atomicAdd(&hist[hi], 1); }
    }
    __syncthreads();
    if (tid < NBIN) sbase[tid] = atomicAdd(&g_binCnt[tid], hist[tid]);
    __syncthreads();
    if (t0i >= 0) {
        int p = sbase[t0i] + s0;
        if (p < BCAP) { g_binZ[t0i * BCAP + p] = zz; g_binI[t0i * BCAP + p] = i; }
    }
    if (t1i >= 0) {
        int p = sbase[t1i] + s1;
        if (p < BCAP) { g_binZ[t1i * BCAP + p] = zz; g_binI[t1i * BCAP + p] = i; }
    }
}

// ======================= waveform kernel: banded GEMM over bins =======================
constexpr int WV_NSL = 24;
constexpr float CNORM = 0.3989422804f;
constexpr float EM1   = 0.36787944117144233f;

constexpr int EST_S = 264;
constexpr int RST_S = 266;
constexpr int WOFF_EST = 0;                          // u16[32*264]
constexpr int WOFF_RST = WOFF_EST + 32 * EST_S * 2;  // u16[64*266]
constexpr int WV_SMEM  = WOFF_RST + 64 * RST_S * 2;  // ~51 KB

__global__ __launch_bounds__(256, 2)
void waveform_gemm(float* __restrict__ out) {
    extern __shared__ unsigned char sm[];
    u16* EST = reinterpret_cast<u16*>(sm + WOFF_EST);
    u16* RST = reinterpret_cast<u16*>(sm + WOFF_RST);

    const int tid  = threadIdx.x;
    const int lane = tid & 31;
    const int wid  = tid >> 5;
    const int g    = lane >> 2, tg = lane & 3;
    const int tile = blockIdx.x;
    const int t0   = tile * 32;

    const int cnt   = min(g_binCnt[tile], BCAP);
    const int per   = (cnt + WV_NSL - 1) / WV_NSL;
    const int mybeg = blockIdx.y * per;
    const int myend = min(mybeg + per, cnt);

    float C[8];
    #pragma unroll
    for (int i = 0; i < 8; i++) C[i] = 0.f;

    const int mt = wid & 3;       // m-tile (16 sensors)
    const int nh = wid >> 2;      // n-half (16 ticks)
    const int em1v = myend - 1;

    for (int cb = mybeg; cb < myend; cb += 256) {
        // ---- build E^T: lane-parallel gaussian recurrence over 32 ticks ----
        {
            const int e = cb + tid;
            const bool valid = (e < myend);
            const float zz = g_binZ[tile * BCAP + min(e, em1v)];
            const int   c  = __float2int_rn(zz);
            const int   js = min(max(c - WV_R - t0, 0), 31);
            const float ds = (float)(t0 + js) - zz;
            const float vm = valid ? 1.f : 0.f;
            const float gst = CNORM * __expf(-0.5f * ds * ds) * vm;
            const float mst = __expf(-ds - 0.5f) * vm;
            float gg = 0.f, mm = 0.f;
            #pragma unroll
            for (int j = 0; j < 32; j++) {
                bool fresh = (j == js);
                gg = fresh ? gst : gg * mm;
                mm = fresh ? mst : mm * EM1;
                EST[j * EST_S + tid] = __bfloat16_as_ushort(__float2bfloat16_rn(gg));
            }
        }
        // ---- gather R rows (all loads issued up front), then transpose-stage ----
        {
            uint32 va[16], vb[16];
            #pragma unroll
            for (int r2 = 0; r2 < 16; r2++) {
                const int e0 = cb + wid * 32 + 2 * r2;
                const int i0 = g_binI[tile * BCAP + min(e0, em1v)];
                const int i1 = g_binI[tile * BCAP + min(e0 + 1, em1v)];
                va[r2] = g_R32[(size_t)i0 * 32 + lane];
                vb[r2] = g_R32[(size_t)i1 * 32 + lane];
            }
            #pragma unroll
            for (int r2 = 0; r2 < 16; r2++) {
                const int le0 = wid * 32 + 2 * r2;
                const uint32 lo = __byte_perm(va[r2], vb[r2], 0x5410);
                const uint32 hi = __byte_perm(va[r2], vb[r2], 0x7632);
                *reinterpret_cast<uint32*>(RST + (2 * lane) * RST_S + le0)     = lo;
                *reinterpret_cast<uint32*>(RST + (2 * lane + 1) * RST_S + le0) = hi;
            }
        }
        __syncthreads();

        // ---- GEMM: C += R^T @ E over K=256 ----
        #pragma unroll
        for (int ks = 0; ks < 16; ks++) {
            const int kb = ks * 16 + 2 * tg;
            const u16* Ar0 = RST + (mt * 16 + g) * RST_S + kb;
            const u16* Ar1 = RST + (mt * 16 + g + 8) * RST_S + kb;
            uint32 a0 = *reinterpret_cast<const uint32*>(Ar0);
            uint32 a1 = *reinterpret_cast<const uint32*>(Ar1);
            uint32 a2 = *reinterpret_cast<const uint32*>(Ar0 + 8);
            uint32 a3 = *reinterpret_cast<const uint32*>(Ar1 + 8);
            #pragma unroll
            for (int nt = 0; nt < 2; nt++) {
                const u16* Bp = EST + ((nh * 2 + nt) * 8 + g) * EST_S + kb;
                uint32 b0 = *reinterpret_cast<const uint32*>(Bp);
                uint32 b1 = *reinterpret_cast<const uint32*>(Bp + 8);
                mma16816(&C[nt * 4], a0, a1, a2, a3, b0, b1);
            }
        }
        __syncthreads();
    }

    // ---- epilogue: scatter C fragments via atomics ----
    #pragma unroll
    for (int nt = 0; nt < 2; nt++) {
        const int tcol = t0 + (nh * 2 + nt) * 8 + 2 * tg;
        const int srow = mt * 16 + g;
        atomicAdd(&out[srow * 1024 + tcol],           C[nt * 4 + 0]);
        atomicAdd(&out[srow * 1024 + tcol + 1],       C[nt * 4 + 1]);
        atomicAdd(&out[(srow + 8) * 1024 + tcol],     C[nt * 4 + 2]);
        atomicAdd(&out[(srow + 8) * 1024 + tcol + 1], C[nt * 4 + 3]);
    }
}

// ---------------- launch ----------------
extern "C" void kernel_launch(void* const* d_in, const int* in_sizes, int n_in,
                              void* d_out, int out_size) {
    const float*  photons = (const float*)d_in[0];
    const float2* xy      = (const float2*)d_in[1];
    const float*  zpos    = (const float*)d_in[2];
    const float*  W1      = (const float*)d_in[3];
    const float*  b1      = (const float*)d_in[4];
    const float*  W2      = (const float*)d_in[5];
    const float*  b2      = (const float*)d_in[6];
    const float*  W3      = (const float*)d_in[7];
    const float*  b3      = (const float*)d_in[8];
    float* out = (float*)d_out;

    cudaFuncSetAttribute(mlp_kernel, cudaFuncAttributeMaxDynamicSharedMemorySize, MLP_SMEM);
    cudaFuncSetAttribute(waveform_gemm, cudaFuncAttributeMaxDynamicSharedMemorySize, WV_SMEM);

    zero_kernel<<<SENS, 1024>>>(out);                          // out + bin counts
    bin_kernel<<<(N_EL + 255) / 256, 256>>>(zpos);             // per-tile lists
    mlp_kernel<<<MLP_GRID, 256, MLP_SMEM>>>(photons, xy, W1, b1, W2, b2, W3, b3);

    dim3 wgrid(TICKS / 32, WV_NSL);
    waveform_gemm<<<wgrid, 256, WV_SMEM>>>(out);
}

// round 7
// speedup vs baseline: 3.8418x; 1.1107x over previous
#include <cuda_runtime.h>
#include <cuda_bf16.h>

typedef unsigned int uint32;
typedef unsigned short u16;

// ---------------- problem constants ----------------
constexpr int N_EL  = 300000;
constexpr int SENS  = 64;
constexpr int TICKS = 1024;
constexpr int HID   = 128;

// ---------------- global scratch ----------------
__device__ uint32 g_R32[(size_t)N_EL * (SENS / 2)];   // response bf16x2 [N][32]

constexpr int NBIN = 32;       // 32-tick tiles
constexpr int BCAP = 16384;
constexpr int WV_R = 5;        // gaussian inclusion radius (ticks)
__device__ float g_binZ[NBIN * BCAP];
__device__ int   g_binI[NBIN * BCAP];
__device__ int   g_binCnt[NBIN];

// ---------------- helpers ----------------
__device__ __forceinline__ void mma16816(float* c, uint32 a0, uint32 a1, uint32 a2, uint32 a3,
                                         uint32 b0, uint32 b1) {
    asm volatile(
        "mma.sync.aligned.m16n8k16.row.col.f32.bf16.bf16.f32 "
        "{%0,%1,%2,%3},{%4,%5,%6,%7},{%8,%9},{%0,%1,%2,%3};\n"
        : "+f"(c[0]), "+f"(c[1]), "+f"(c[2]), "+f"(c[3])
        : "r"(a0), "r"(a1), "r"(a2), "r"(a3), "r"(b0), "r"(b1));
}

__device__ __forceinline__ void ldsm4(uint32& r0, uint32& r1, uint32& r2, uint32& r3,
                                      uint32 addr) {
    asm volatile("ldmatrix.sync.aligned.m8n8.x4.shared.b16 {%0,%1,%2,%3}, [%4];"
        : "=r"(r0), "=r"(r1), "=r"(r2), "=r"(r3) : "r"(addr));
}

__device__ __forceinline__ void ldsm4t(uint32& r0, uint32& r1, uint32& r2, uint32& r3,
                                       uint32 addr) {
    asm volatile("ldmatrix.sync.aligned.m8n8.x4.trans.shared.b16 {%0,%1,%2,%3}, [%4];"
        : "=r"(r0), "=r"(r1), "=r"(r2), "=r"(r3) : "r"(addr));
}

__device__ __forceinline__ uint32 smem_u32(const void* p) {
    uint32 a;
    asm("{ .reg .u64 t; cvta.to.shared.u64 t, %1; cvt.u32.u64 %0, t; }" : "=r"(a) : "l"(p));
    return a;
}

__device__ __forceinline__ uint32 packbf2(float a, float b) {
    __nv_bfloat162 t = __floats2bfloat162_rn(a, b);
    return *reinterpret_cast<uint32*>(&t);
}

// FFMA-only sigmoid (no MUFU), 2 Newton steps (rel err ~1e-6)
__device__ __forceinline__ float fast_sigmoid(float x) {
    float y = fminf(fmaxf(x, -15.f), 15.f) * 1.44269504f;
    float t = __fadd_rn(y, 12582912.f);
    int   n = __float_as_int(t) - 0x4B400000;
    float f = y - __fsub_rn(t, 12582912.f);
    float p = 0.0013333558f;
    p = fmaf(p, f, 0.0096181291f);
    p = fmaf(p, f, 0.0555041087f);
    p = fmaf(p, f, 0.2402265070f);
    p = fmaf(p, f, 0.6931471806f);
    p = fmaf(p, f, 1.0f);
    float z = __int_as_float(__float_as_int(p) + (n << 23));
    float a = 1.f + z;
    float r = __int_as_float(0x7EF311C3 - __float_as_int(a));
    r = r * (2.f - a * r);
    r = r * (2.f - a * r);
    return z * r;
}

// ======================= MLP kernel (unchanged from R5 pass) =======================
constexpr int KP  = 136;
constexpr int NWT = N_EL / 16;       // 18750
constexpr int MLP_GRID = 296;

constexpr int OFF_W2T = 0;                          // [128][KP] bf16 = 34816 B
constexpr int OFF_W3T = OFF_W2T + HID * KP * 2;     // [64][KP]  bf16 = 17408 B
constexpr int OFF_W1E = OFF_W3T + SENS * KP * 2;    // [128][16] bf16 = 4096 B
constexpr int OFF_B2  = OFF_W1E + 128 * 16 * 2;     // float[128]
constexpr int OFF_B3  = OFF_B2 + 128 * 4;           // float[64]
constexpr int MLP_SMEM = OFF_B3 + 64 * 4;           // ~57 KB

__global__ __launch_bounds__(256, 2)
void mlp_kernel(const float* __restrict__ photons,
                const float2* __restrict__ xy,
                const float* __restrict__ W1, const float* __restrict__ b1,
                const float* __restrict__ W2, const float* __restrict__ b2,
                const float* __restrict__ W3, const float* __restrict__ b3) {
    extern __shared__ unsigned char sm[];
    __nv_bfloat16* sW2t = reinterpret_cast<__nv_bfloat16*>(sm + OFF_W2T);
    __nv_bfloat16* sW3t = reinterpret_cast<__nv_bfloat16*>(sm + OFF_W3T);
    __nv_bfloat16* sW1e = reinterpret_cast<__nv_bfloat16*>(sm + OFF_W1E);
    float* sB2 = reinterpret_cast<float*>(sm + OFF_B2);
    float* sB3 = reinterpret_cast<float*>(sm + OFF_B3);

    const int tid = threadIdx.x;
    for (int i = tid; i < HID * HID; i += 256) {
        int k = i >> 7, n = i & 127;
        sW2t[n * KP + k] = __float2bfloat16_rn(W2[i]);
    }
    for (int i = tid; i < HID * SENS; i += 256) {
        int k = i >> 6, n = i & 63;
        sW3t[n * KP + k] = __float2bfloat16_rn(W3[i]);
    }
    for (int i = tid; i < 128 * 16; i += 256) {
        int n = i >> 4, k = i & 15;
        float v = (k == 0) ? W1[n] : (k == 1) ? W1[128 + n] : (k == 2) ? b1[n] : 0.f;
        sW1e[i] = __float2bfloat16_rn(v);
    }
    if (tid < 128) sB2[tid] = b2[tid];
    if (tid < 64)  sB3[tid] = b3[tid];
    __syncthreads();

    const int wid = tid >> 5, lane = tid & 31;
    const int g = lane >> 2, tg = lane & 3;
    const int kq = tg * 2;

    const int row_in = (lane & 7) + ((lane >> 4) << 3);
    const int k8off  = (lane >> 3) & 1;
    const uint32 lmB2 = smem_u32(sW2t) + (uint32)(row_in * (KP * 2) + k8off * 16);
    const uint32 lmB3 = smem_u32(sW3t) + (uint32)(row_in * (KP * 2) + k8off * 16);

    const int wslot   = blockIdx.x * 8 + wid;
    const int wstride = gridDim.x * 8;

    for (int wt = wslot; wt < NWT; wt += wstride) {
        const int r0 = wt * 16 + g, r1 = r0 + 8;
        const float2 p0 = xy[r0], p1 = xy[r1];
        const float ph0 = photons[r0], ph1 = photons[r1];

        float acc1[64];
        #pragma unroll
        for (int i = 0; i < 64; i++) acc1[i] = 0.f;
        const uint32 xa0 = (tg == 0) ? packbf2(p0.x, p0.y) : ((tg == 1) ? 0x00003F80u : 0u);
        const uint32 xa1 = (tg == 0) ? packbf2(p1.x, p1.y) : ((tg == 1) ? 0x00003F80u : 0u);
        #pragma unroll
        for (int nt = 0; nt < 16; nt++) {
            uint32 b0 = *reinterpret_cast<const uint32*>(sW1e + (nt * 8 + g) * 16 + kq);
            mma16816(&acc1[nt * 4], xa0, xa1, 0u, 0u, b0, 0u);
        }

        uint32 A2[32];
        #pragma unroll
        for (int kt = 0; kt < 8; kt++) {
            A2[kt * 4 + 0] = packbf2(fmaxf(acc1[8 * kt + 0], 0.f), fmaxf(acc1[8 * kt + 1], 0.f));
            A2[kt * 4 + 1] = packbf2(fmaxf(acc1[8 * kt + 2], 0.f), fmaxf(acc1[8 * kt + 3], 0.f));
            A2[kt * 4 + 2] = packbf2(fmaxf(acc1[8 * kt + 4], 0.f), fmaxf(acc1[8 * kt + 5], 0.f));
            A2[kt * 4 + 3] = packbf2(fmaxf(acc1[8 * kt + 6], 0.f), fmaxf(acc1[8 * kt + 7], 0.f));
        }

        float acc2[64];
        #pragma unroll
        for (int i = 0; i < 64; i++) acc2[i] = 0.f;
        #pragma unroll
        for (int kt = 0; kt < 8; kt++) {
            #pragma unroll
            for (int p = 0; p < 8; p++) {
                uint32 b0, b1r, b2r, b3r;
                ldsm4(b0, b1r, b2r, b3r, lmB2 + (uint32)(p * 16 * (KP * 2) + kt * 32));
                mma16816(&acc2[(2 * p) * 4], A2[kt * 4 + 0], A2[kt * 4 + 1],
                         A2[kt * 4 + 2], A2[kt * 4 + 3], b0, b1r);
                mma16816(&acc2[(2 * p + 1) * 4], A2[kt * 4 + 0], A2[kt * 4 + 1],
                         A2[kt * 4 + 2], A2[kt * 4 + 3], b2r, b3r);
            }
        }

        uint32 A3[32];
        #pragma unroll
        for (int kt = 0; kt < 8; kt++) {
            const int nt0 = 2 * kt, nt1 = nt0 + 1;
            const int c0 = nt0 * 8 + kq, c1 = nt1 * 8 + kq;
            float b20 = sB2[c0], b21 = sB2[c0 + 1];
            float b22 = sB2[c1], b23 = sB2[c1 + 1];
            A3[kt * 4 + 0] = packbf2(fmaxf(acc2[nt0 * 4 + 0] + b20, 0.f),
                                     fmaxf(acc2[nt0 * 4 + 1] + b21, 0.f));
            A3[kt * 4 + 1] = packbf2(fmaxf(acc2[nt0 * 4 + 2] + b20, 0.f),
                                     fmaxf(acc2[nt0 * 4 + 3] + b21, 0.f));
            A3[kt * 4 + 2] = packbf2(fmaxf(acc2[nt1 * 4 + 0] + b22, 0.f),
                                     fmaxf(acc2[nt1 * 4 + 1] + b23, 0.f));
            A3[kt * 4 + 3] = packbf2(fmaxf(acc2[nt1 * 4 + 2] + b22, 0.f),
                                     fmaxf(acc2[nt1 * 4 + 3] + b23, 0.f));
        }

        float acc3[32];
        #pragma unroll
        for (int i = 0; i < 32; i++) acc3[i] = 0.f;
        #pragma unroll
        for (int kt = 0; kt < 8; kt++) {
            #pragma unroll
            for (int p = 0; p < 4; p++) {
                uint32 b0, b1r, b2r, b3r;
                ldsm4(b0, b1r, b2r, b3r, lmB3 + (uint32)(p * 16 * (KP * 2) + kt * 32));
                mma16816(&acc3[(2 * p) * 4], A3[kt * 4 + 0], A3[kt * 4 + 1],
                         A3[kt * 4 + 2], A3[kt * 4 + 3], b0, b1r);
                mma16816(&acc3[(2 * p + 1) * 4], A3[kt * 4 + 0], A3[kt * 4 + 1],
                         A3[kt * 4 + 2], A3[kt * 4 + 3], b2r, b3r);
            }
        }

        #pragma unroll
        for (int nt = 0; nt < 8; nt++) {
            const int c0 = nt * 8 + kq;
            float bb0 = sB3[c0], bb1 = sB3[c0 + 1];
            float s0 = fast_sigmoid(acc3[nt * 4 + 0] + bb0);
            float s1 = fast_sigmoid(acc3[nt * 4 + 1] + bb1);
            float s2 = fast_sigmoid(acc3[nt * 4 + 2] + bb0);
            float s3 = fast_sigmoid(acc3[nt * 4 + 3] + bb1);
            g_R32[(size_t)r0 * 32 + nt * 4 + tg] = packbf2(ph0 * s0, ph0 * s1);
            g_R32[(size_t)r1 * 32 + nt * 4 + tg] = packbf2(ph1 * s2, ph1 * s3);
        }
    }
}

// ---------------- output zeroing + bin-count reset ----------------
__global__ void zero_kernel(float* __restrict__ out) {
    int i = blockIdx.x * 1024 + threadIdx.x;
    out[i] = 0.f;
    if (i < NBIN) g_binCnt[i] = 0;
}

// ---------------- binning kernel ----------------
__global__ __launch_bounds__(256)
void bin_kernel(const float* __restrict__ zpos) {
    __shared__ int hist[NBIN], sbase[NBIN];
    const int tid = threadIdx.x;
    if (tid < NBIN) hist[tid] = 0;
    __syncthreads();

    const int i = blockIdx.x * 256 + tid;
    float zz = 0.f;
    int t0i = -1, t1i = -1, s0 = 0, s1 = 0;
    if (i < N_EL) {
        zz = zpos[i];
        int c = __float2int_rn(zz);
        int lo = max(c - WV_R, 0) >> 5;
        int hi = min(c + WV_R, TICKS - 1) >> 5;
        t0i = lo; s0 = atomicAdd(&hist[lo], 1);
        if (hi != lo) { t1i = hi; s1 = atomicAdd(&hist[hi], 1); }
    }
    __syncthreads();
    if (tid < NBIN) sbase[tid] = atomicAdd(&g_binCnt[tid], hist[tid]);
    __syncthreads();
    if (t0i >= 0) {
        int p = sbase[t0i] + s0;
        if (p < BCAP) { g_binZ[t0i * BCAP + p] = zz; g_binI[t0i * BCAP + p] = i; }
    }
    if (t1i >= 0) {
        int p = sbase[t1i] + s1;
        if (p < BCAP) { g_binZ[t1i * BCAP + p] = zz; g_binI[t1i * BCAP + p] = i; }
    }
}

// ======================= waveform kernel: banded GEMM over bins =======================
// Whole 256-electron chunks round-robin over blockIdx.y. R staged UNtransposed
// [electron][sensor] (144B rows, 16B-aligned); A fragments via ldmatrix.x4.trans,
// B fragments via ldmatrix.x4.
constexpr int WV_NSL = 24;
constexpr float CNORM = 0.3989422804f;
constexpr float EM1   = 0.36787944117144233f;

constexpr int EST_S = 264;   // u16 row stride (528 B = 33*16, aligned + conflict-free)
constexpr int RS2_S = 72;    // u16 row stride (144 B = 9*16, aligned + conflict-free)
constexpr int WOFF_EST = 0;                          // u16[32*264]  = 16896 B
constexpr int WOFF_RS2 = WOFF_EST + 32 * EST_S * 2;  // u16[256*72]  = 36864 B
constexpr int WV_SMEM  = WOFF_RS2 + 256 * RS2_S * 2; // ~52.5 KB

__global__ __launch_bounds__(256, 2)
void waveform_gemm(float* __restrict__ out) {
    extern __shared__ unsigned char sm[];
    u16*    EST  = reinterpret_cast<u16*>(sm + WOFF_EST);
    uint32* RS2w = reinterpret_cast<uint32*>(sm + WOFF_RS2);

    const int tid  = threadIdx.x;
    const int lane = tid & 31;
    const int wid  = tid >> 5;
    const int g    = lane >> 2, tg = lane & 3;
    const int tile = blockIdx.x;
    const int t0   = tile * 32;

    const int cnt = min(g_binCnt[tile], BCAP);
    const int nc  = (cnt + 255) >> 8;       // whole chunks
    const int emax = cnt - 1;

    float C[8];
    #pragma unroll
    for (int i = 0; i < 8; i++) C[i] = 0.f;

    const int mt = wid & 3;       // m-tile (16 sensors)
    const int nh = wid >> 2;      // n-half (16 ticks)

    // A (trans): tile rows = electrons (k), cols = sensors (m).
    // lane 0-7: rows k0-7 col m+0 | 8-15: k0-7 col m+8 | 16-23: k8-15 col m+0 | 24-31: k8-15 col m+8
    const int arow = (lane & 7) + ((lane >> 4) << 3);
    const int acol = mt * 16 + ((lane >> 3) & 1) * 8;
    const uint32 lmA = smem_u32(sm + WOFF_RS2) + (uint32)((arow * RS2_S + acol) * 2);
    // B: rows = ticks (n), cols = electrons (k)
    const int rowB = (lane & 7) + ((lane >> 4) << 3);
    const uint32 lmB = smem_u32(sm + WOFF_EST) +
        (uint32)(((nh * 16 + rowB) * EST_S + (((lane >> 3) & 1) * 8)) * 2);

    for (int c = blockIdx.y; c < nc; c += WV_NSL) {
        const int cb = c << 8;
        const int cend = min(cb + 256, cnt);

        // ---- build E^T: lane-parallel gaussian recurrence over 32 ticks ----
        {
            const int e = cb + tid;
            const bool valid = (e < cend);
            const float zz = g_binZ[tile * BCAP + min(e, emax)];
            const int   ci = __float2int_rn(zz);
            const int   js = min(max(ci - WV_R - t0, 0), 31);
            const float ds = (float)(t0 + js) - zz;
            const float vm = valid ? 1.f : 0.f;
            const float gst = CNORM * __expf(-0.5f * ds * ds) * vm;
            const float mst = __expf(-ds - 0.5f) * vm;
            float gg = 0.f, mm = 0.f;
            #pragma unroll
            for (int j = 0; j < 32; j++) {
                bool fresh = (j == js);
                gg = fresh ? gst : gg * mm;
                mm = fresh ? mst : mm * EM1;
                EST[j * EST_S + tid] = __bfloat16_as_ushort(__float2bfloat16_rn(gg));
            }
        }
        // ---- gather R rows -> RS2 [electron][sensor], conflict-free stores ----
        {
            #pragma unroll
            for (int rb = 0; rb < 4; rb++) {
                int ixs[8];
                #pragma unroll
                for (int r = 0; r < 8; r++) {
                    const int e = cb + wid * 32 + rb * 8 + r;
                    ixs[r] = g_binI[tile * BCAP + min(e, emax)];
                }
                uint32 v[8];
                #pragma unroll
                for (int r = 0; r < 8; r++)
                    v[r] = g_R32[(size_t)ixs[r] * 32 + lane];
                #pragma unroll
                for (int r = 0; r < 8; r++) {
                    const int le = wid * 32 + rb * 8 + r;
                    RS2w[le * (RS2_S / 2) + lane] = v[r];
                }
            }
        }
        __syncthreads();

        // ---- GEMM: C += R^T @ E over K=256 (A via ldsm.trans, B via ldsm) ----
        #pragma unroll
        for (int ks = 0; ks < 16; ks++) {
            uint32 a0, a1, a2, a3, b0, b1, b2, b3;
            ldsm4t(a0, a1, a2, a3, lmA + (uint32)(ks * 16 * RS2_S * 2));
            ldsm4 (b0, b1, b2, b3, lmB + (uint32)(ks * 32));
            mma16816(&C[0], a0, a1, a2, a3, b0, b1);
            mma16816(&C[4], a0, a1, a2, a3, b2, b3);
        }
        __syncthreads();
    }

    // ---- epilogue: scatter C fragments via atomics ----
    #pragma unroll
    for (int nt = 0; nt < 2; nt++) {
        const int tcol = t0 + (nh * 2 + nt) * 8 + 2 * tg;
        const int srow = mt * 16 + g;
        atomicAdd(&out[srow * 1024 + tcol],           C[nt * 4 + 0]);
        atomicAdd(&out[srow * 1024 + tcol + 1],       C[nt * 4 + 1]);
        atomicAdd(&out[(srow + 8) * 1024 + tcol],     C[nt * 4 + 2]);
        atomicAdd(&out[(srow + 8) * 1024 + tcol + 1], C[nt * 4 + 3]);
    }
}

// ---------------- launch ----------------
extern "C" void kernel_launch(void* const* d_in, const int* in_sizes, int n_in,
                              void* d_out, int out_size) {
    const float*  photons = (const float*)d_in[0];
    const float2* xy      = (const float2*)d_in[1];
    const float*  zpos    = (const float*)d_in[2];
    const float*  W1      = (const float*)d_in[3];
    const float*  b1      = (const float*)d_in[4];
    const float*  W2      = (const float*)d_in[5];
    const float*  b2      = (const float*)d_in[6];
    const float*  W3      = (const float*)d_in[7];
    const float*  b3      = (const float*)d_in[8];
    float* out = (float*)d_out;

    cudaFuncSetAttribute(mlp_kernel, cudaFuncAttributeMaxDynamicSharedMemorySize, MLP_SMEM);
    cudaFuncSetAttribute(waveform_gemm, cudaFuncAttributeMaxDynamicSharedMemorySize, WV_SMEM);

    zero_kernel<<<SENS, 1024>>>(out);
    bin_kernel<<<(N_EL + 255) / 256, 256>>>(zpos);
    mlp_kernel<<<MLP_GRID, 256, MLP_SMEM>>>(photons, xy, W1, b1, W2, b2, W3, b3);

    dim3 wgrid(TICKS / 32, WV_NSL);
    waveform_gemm<<<wgrid, 256, WV_SMEM>>>(out);
}

// round 8
// speedup vs baseline: 3.9027x; 1.0159x over previous
#include <cuda_runtime.h>
#include <cuda_bf16.h>

typedef unsigned int uint32;
typedef unsigned short u16;

// ---------------- problem constants ----------------
constexpr int N_EL  = 300000;
constexpr int SENS  = 64;
constexpr int TICKS = 1024;
constexpr int HID   = 128;

// ---------------- global scratch ----------------
__device__ uint32 g_R32[(size_t)N_EL * (SENS / 2)];   // response bf16x2 [N][32]

constexpr int NBIN = 32;       // 32-tick tiles
constexpr int BCAP = 16384;
constexpr int WV_R = 5;        // gaussian inclusion radius (ticks)
__device__ float g_binZ[NBIN * BCAP];
__device__ int   g_binI[NBIN * BCAP];
__device__ int   g_binCnt[NBIN];

// ---------------- helpers ----------------
__device__ __forceinline__ void mma16816(float* c, uint32 a0, uint32 a1, uint32 a2, uint32 a3,
                                         uint32 b0, uint32 b1) {
    asm volatile(
        "mma.sync.aligned.m16n8k16.row.col.f32.bf16.bf16.f32 "
        "{%0,%1,%2,%3},{%4,%5,%6,%7},{%8,%9},{%0,%1,%2,%3};\n"
        : "+f"(c[0]), "+f"(c[1]), "+f"(c[2]), "+f"(c[3])
        : "r"(a0), "r"(a1), "r"(a2), "r"(a3), "r"(b0), "r"(b1));
}

__device__ __forceinline__ void ldsm4(uint32& r0, uint32& r1, uint32& r2, uint32& r3,
                                      uint32 addr) {
    asm volatile("ldmatrix.sync.aligned.m8n8.x4.shared.b16 {%0,%1,%2,%3}, [%4];"
        : "=r"(r0), "=r"(r1), "=r"(r2), "=r"(r3) : "r"(addr));
}

__device__ __forceinline__ void ldsm4t(uint32& r0, uint32& r1, uint32& r2, uint32& r3,
                                       uint32 addr) {
    asm volatile("ldmatrix.sync.aligned.m8n8.x4.trans.shared.b16 {%0,%1,%2,%3}, [%4];"
        : "=r"(r0), "=r"(r1), "=r"(r2), "=r"(r3) : "r"(addr));
}

__device__ __forceinline__ uint32 smem_u32(const void* p) {
    uint32 a;
    asm("{ .reg .u64 t; cvta.to.shared.u64 t, %1; cvt.u32.u64 %0, t; }" : "=r"(a) : "l"(p));
    return a;
}

__device__ __forceinline__ uint32 packbf2(float a, float b) {
    __nv_bfloat162 t = __floats2bfloat162_rn(a, b);
    return *reinterpret_cast<uint32*>(&t);
}

// MUFU-based sigmoid: EX2 + RCP (~5 issues)
__device__ __forceinline__ float sigmoid_mufu(float x) {
    return __fdividef(1.f, 1.f + __expf(-x));
}

// ======================= MLP kernel =======================
constexpr int KP  = 136;
constexpr int NWT = N_EL / 16;       // 18750
constexpr int MLP_GRID = 296;

constexpr int OFF_W2T = 0;                          // [128][KP] bf16 = 34816 B
constexpr int OFF_W3T = OFF_W2T + HID * KP * 2;     // [64][KP]  bf16 = 17408 B
constexpr int OFF_W1E = OFF_W3T + SENS * KP * 2;    // [128][16] bf16 = 4096 B
constexpr int OFF_B2  = OFF_W1E + 128 * 16 * 2;     // float[128]
constexpr int OFF_B3  = OFF_B2 + 128 * 4;           // float[64]
constexpr int MLP_SMEM = OFF_B3 + 64 * 4;           // ~57 KB

__global__ __launch_bounds__(256, 2)
void mlp_kernel(const float* __restrict__ photons,
                const float2* __restrict__ xy,
                const float* __restrict__ W1, const float* __restrict__ b1,
                const float* __restrict__ W2, const float* __restrict__ b2,
                const float* __restrict__ W3, const float* __restrict__ b3) {
    extern __shared__ unsigned char sm[];
    __nv_bfloat16* sW2t = reinterpret_cast<__nv_bfloat16*>(sm + OFF_W2T);
    __nv_bfloat16* sW3t = reinterpret_cast<__nv_bfloat16*>(sm + OFF_W3T);
    __nv_bfloat16* sW1e = reinterpret_cast<__nv_bfloat16*>(sm + OFF_W1E);
    float* sB2 = reinterpret_cast<float*>(sm + OFF_B2);
    float* sB3 = reinterpret_cast<float*>(sm + OFF_B3);

    const int tid = threadIdx.x;
    for (int i = tid; i < HID * HID; i += 256) {
        int k = i >> 7, n = i & 127;
        sW2t[n * KP + k] = __float2bfloat16_rn(W2[i]);
    }
    for (int i = tid; i < HID * SENS; i += 256) {
        int k = i >> 6, n = i & 63;
        sW3t[n * KP + k] = __float2bfloat16_rn(W3[i]);
    }
    for (int i = tid; i < 128 * 16; i += 256) {
        int n = i >> 4, k = i & 15;
        float v = (k == 0) ? W1[n] : (k == 1) ? W1[128 + n] : (k == 2) ? b1[n] : 0.f;
        sW1e[i] = __float2bfloat16_rn(v);
    }
    if (tid < 128) sB2[tid] = b2[tid];
    if (tid < 64)  sB3[tid] = b3[tid];
    __syncthreads();

    const int wid = tid >> 5, lane = tid & 31;
    const int g = lane >> 2, tg = lane & 3;
    const int kq = tg * 2;

    const int row_in = (lane & 7) + ((lane >> 4) << 3);
    const int k8off  = (lane >> 3) & 1;
    const uint32 lmB2 = smem_u32(sW2t) + (uint32)(row_in * (KP * 2) + k8off * 16);
    const uint32 lmB3 = smem_u32(sW3t) + (uint32)(row_in * (KP * 2) + k8off * 16);

    const int wslot   = blockIdx.x * 8 + wid;
    const int wstride = gridDim.x * 8;

    for (int wt = wslot; wt < NWT; wt += wstride) {
        const int r0 = wt * 16 + g, r1 = r0 + 8;
        const float2 p0 = xy[r0], p1 = xy[r1];
        const float ph0 = photons[r0], ph1 = photons[r1];

        float acc1[64];
        #pragma unroll
        for (int i = 0; i < 64; i++) acc1[i] = 0.f;
        const uint32 xa0 = (tg == 0) ? packbf2(p0.x, p0.y) : ((tg == 1) ? 0x00003F80u : 0u);
        const uint32 xa1 = (tg == 0) ? packbf2(p1.x, p1.y) : ((tg == 1) ? 0x00003F80u : 0u);
        #pragma unroll
        for (int nt = 0; nt < 16; nt++) {
            uint32 b0 = *reinterpret_cast<const uint32*>(sW1e + (nt * 8 + g) * 16 + kq);
            mma16816(&acc1[nt * 4], xa0, xa1, 0u, 0u, b0, 0u);
        }

        uint32 A2[32];
        #pragma unroll
        for (int kt = 0; kt < 8; kt++) {
            A2[kt * 4 + 0] = packbf2(fmaxf(acc1[8 * kt + 0], 0.f), fmaxf(acc1[8 * kt + 1], 0.f));
            A2[kt * 4 + 1] = packbf2(fmaxf(acc1[8 * kt + 2], 0.f), fmaxf(acc1[8 * kt + 3], 0.f));
            A2[kt * 4 + 2] = packbf2(fmaxf(acc1[8 * kt + 4], 0.f), fmaxf(acc1[8 * kt + 5], 0.f));
            A2[kt * 4 + 3] = packbf2(fmaxf(acc1[8 * kt + 6], 0.f), fmaxf(acc1[8 * kt + 7], 0.f));
        }

        float acc2[64];
        #pragma unroll
        for (int i = 0; i < 64; i++) acc2[i] = 0.f;
        #pragma unroll
        for (int kt = 0; kt < 8; kt++) {
            #pragma unroll
            for (int p = 0; p < 8; p++) {
                uint32 b0, b1r, b2r, b3r;
                ldsm4(b0, b1r, b2r, b3r, lmB2 + (uint32)(p * 16 * (KP * 2) + kt * 32));
                mma16816(&acc2[(2 * p) * 4], A2[kt * 4 + 0], A2[kt * 4 + 1],
                         A2[kt * 4 + 2], A2[kt * 4 + 3], b0, b1r);
                mma16816(&acc2[(2 * p + 1) * 4], A2[kt * 4 + 0], A2[kt * 4 + 1],
                         A2[kt * 4 + 2], A2[kt * 4 + 3], b2r, b3r);
            }
        }

        uint32 A3[32];
        #pragma unroll
        for (int kt = 0; kt < 8; kt++) {
            const int nt0 = 2 * kt, nt1 = nt0 + 1;
            const int c0 = nt0 * 8 + kq, c1 = nt1 * 8 + kq;
            float b20 = sB2[c0], b21 = sB2[c0 + 1];
            float b22 = sB2[c1], b23 = sB2[c1 + 1];
            A3[kt * 4 + 0] = packbf2(fmaxf(acc2[nt0 * 4 + 0] + b20, 0.f),
                                     fmaxf(acc2[nt0 * 4 + 1] + b21, 0.f));
            A3[kt * 4 + 1] = packbf2(fmaxf(acc2[nt0 * 4 + 2] + b20, 0.f),
                                     fmaxf(acc2[nt0 * 4 + 3] + b21, 0.f));
            A3[kt * 4 + 2] = packbf2(fmaxf(acc2[nt1 * 4 + 0] + b22, 0.f),
                                     fmaxf(acc2[nt1 * 4 + 1] + b23, 0.f));
            A3[kt * 4 + 3] = packbf2(fmaxf(acc2[nt1 * 4 + 2] + b22, 0.f),
                                     fmaxf(acc2[nt1 * 4 + 3] + b23, 0.f));
        }

        float acc3[32];
        #pragma unroll
        for (int i = 0; i < 32; i++) acc3[i] = 0.f;
        #pragma unroll
        for (int kt = 0; kt < 8; kt++) {
            #pragma unroll
            for (int p = 0; p < 4; p++) {
                uint32 b0, b1r, b2r, b3r;
                ldsm4(b0, b1r, b2r, b3r, lmB3 + (uint32)(p * 16 * (KP * 2) + kt * 32));
                mma16816(&acc3[(2 * p) * 4], A3[kt * 4 + 0], A3[kt * 4 + 1],
                         A3[kt * 4 + 2], A3[kt * 4 + 3], b0, b1r);
                mma16816(&acc3[(2 * p + 1) * 4], A3[kt * 4 + 0], A3[kt * 4 + 1],
                         A3[kt * 4 + 2], A3[kt * 4 + 3], b2r, b3r);
            }
        }

        #pragma unroll
        for (int nt = 0; nt < 8; nt++) {
            const int c0 = nt * 8 + kq;
            float bb0 = sB3[c0], bb1 = sB3[c0 + 1];
            float s0 = sigmoid_mufu(acc3[nt * 4 + 0] + bb0);
            float s1 = sigmoid_mufu(acc3[nt * 4 + 1] + bb1);
            float s2 = sigmoid_mufu(acc3[nt * 4 + 2] + bb0);
            float s3 = sigmoid_mufu(acc3[nt * 4 + 3] + bb1);
            g_R32[(size_t)r0 * 32 + nt * 4 + tg] = packbf2(ph0 * s0, ph0 * s1);
            g_R32[(size_t)r1 * 32 + nt * 4 + tg] = packbf2(ph1 * s2, ph1 * s3);
        }
    }
}

// ---------------- output zeroing + bin-count reset (vectorized) ----------------
__global__ void zero_kernel(float4* __restrict__ out) {
    int i = blockIdx.x * 256 + threadIdx.x;
    out[i] = make_float4(0.f, 0.f, 0.f, 0.f);
    if (i < NBIN) g_binCnt[i] = 0;
}

// ---------------- binning kernel ----------------
__global__ __launch_bounds__(256)
void bin_kernel(const float* __restrict__ zpos) {
    __shared__ int hist[NBIN], sbase[NBIN];
    const int tid = threadIdx.x;
    if (tid < NBIN) hist[tid] = 0;
    __syncthreads();

    const int i = blockIdx.x * 256 + tid;
    float zz = 0.f;
    int t0i = -1, t1i = -1, s0 = 0, s1 = 0;
    if (i < N_EL) {
        zz = zpos[i];
        int c = __float2int_rn(zz);
        int lo = max(c - WV_R, 0) >> 5;
        int hi = min(c + WV_R, TICKS - 1) >> 5;
        t0i = lo; s0 = atomicAdd(&hist[lo], 1);
        if (hi != lo) { t1i = hi; s1 = atomicAdd(&hist[hi], 1); }
    }
    __syncthreads();
    if (tid < NBIN) sbase[tid] = atomicAdd(&g_binCnt[tid], hist[tid]);
    __syncthreads();
    if (t0i >= 0) {
        int p = sbase[t0i] + s0;
        if (p < BCAP) { g_binZ[t0i * BCAP + p] = zz; g_binI[t0i * BCAP + p] = i; }
    }
    if (t1i >= 0) {
        int p = sbase[t1i] + s1;
        if (p < BCAP) { g_binZ[t1i * BCAP + p] = zz; g_binI[t1i * BCAP + p] = i; }
    }
}

// ======================= waveform kernel: banded GEMM over bins =======================
constexpr int WV_NSL = 24;
constexpr float CNORM = 0.3989422804f;

constexpr int EST_S = 264;   // u16 row stride (528 B, aligned + conflict-free)
constexpr int RS2_S = 72;    // u16 row stride (144 B, aligned + conflict-free)
constexpr int WOFF_EST = 0;                          // u16[32*264]  = 16896 B
constexpr int WOFF_RS2 = WOFF_EST + 32 * EST_S * 2;  // u16[256*72]  = 36864 B
constexpr int WV_SMEM  = WOFF_RS2 + 256 * RS2_S * 2; // ~52.5 KB

__global__ __launch_bounds__(256, 2)
void waveform_gemm(float* __restrict__ out) {
    extern __shared__ unsigned char sm[];
    u16*    EST  = reinterpret_cast<u16*>(sm + WOFF_EST);
    uint32* RS2w = reinterpret_cast<uint32*>(sm + WOFF_RS2);

    const int tid  = threadIdx.x;
    const int lane = tid & 31;
    const int wid  = tid >> 5;
    const int g    = lane >> 2, tg = lane & 3;
    const int tile = blockIdx.x;
    const int t0   = tile * 32;

    const int cnt = min(g_binCnt[tile], BCAP);
    const int nc  = (cnt + 255) >> 8;       // whole chunks
    const int emax = cnt - 1;

    float C[8];
    #pragma unroll
    for (int i = 0; i < 8; i++) C[i] = 0.f;

    const int mt = wid & 3;       // m-tile (16 sensors)
    const int nh = wid >> 2;      // n-half (16 ticks)

    // A (trans): rows = electrons (k), cols = sensors (m)
    const int arow = (lane & 7) + ((lane >> 4) << 3);
    const int acol = mt * 16 + ((lane >> 3) & 1) * 8;
    const uint32 lmA = smem_u32(sm + WOFF_RS2) + (uint32)((arow * RS2_S + acol) * 2);
    // B: rows = ticks (n), cols = electrons (k)
    const int rowB = (lane & 7) + ((lane >> 4) << 3);
    const uint32 lmB = smem_u32(sm + WOFF_EST) +
        (uint32)(((nh * 16 + rowB) * EST_S + (((lane >> 3) & 1) * 8)) * 2);

    for (int c = blockIdx.y; c < nc; c += WV_NSL) {
        const int cb = c << 8;
        const int cend = min(cb + 256, cnt);

        // ---- build E^T: direct gaussian eval, 32 independent EX2s ----
        {
            const int e = cb + tid;
            const float zz = g_binZ[tile * BCAP + min(e, emax)];
            const float cn = (e < cend) ? CNORM : 0.f;   // zero dup/invalid lanes
            const float d0 = (float)t0 - zz;
            #pragma unroll
            for (int j = 0; j < 32; j++) {
                float d = d0 + (float)j;
                float ex = __expf(-0.5f * d * d);        // underflows to 0 out of range
                EST[j * EST_S + tid] = __bfloat16_as_ushort(__float2bfloat16_rn(cn * ex));
            }
        }
        // ---- gather R rows -> RS2 [electron][sensor], conflict-free stores ----
        {
            #pragma unroll
            for (int rb = 0; rb < 4; rb++) {
                int ixs[8];
                #pragma unroll
                for (int r = 0; r < 8; r++) {
                    const int e = cb + wid * 32 + rb * 8 + r;
                    ixs[r] = g_binI[tile * BCAP + min(e, emax)];
                }
                uint32 v[8];
                #pragma unroll
                for (int r = 0; r < 8; r++)
                    v[r] = g_R32[(size_t)ixs[r] * 32 + lane];
                #pragma unroll
                for (int r = 0; r < 8; r++) {
                    const int le = wid * 32 + rb * 8 + r;
                    RS2w[le * (RS2_S / 2) + lane] = v[r];
                }
            }
        }
        __syncthreads();

        // ---- GEMM: C += R^T @ E over K=256 (A via ldsm.trans, B via ldsm) ----
        #pragma unroll
        for (int ks = 0; ks < 16; ks++) {
            uint32 a0, a1, a2, a3, b0, b1, b2, b3;
            ldsm4t(a0, a1, a2, a3, lmA + (uint32)(ks * 16 * RS2_S * 2));
            ldsm4 (b0, b1, b2, b3, lmB + (uint32)(ks * 32));
            mma16816(&C[0], a0, a1, a2, a3, b0, b1);
            mma16816(&C[4], a0, a1, a2, a3, b2, b3);
        }
        __syncthreads();
    }

    // ---- epilogue: scatter C fragments via atomics ----
    #pragma unroll
    for (int nt = 0; nt < 2; nt++) {
        const int tcol = t0 + (nh * 2 + nt) * 8 + 2 * tg;
        const int srow = mt * 16 + g;
        atomicAdd(&out[srow * 1024 + tcol],           C[nt * 4 + 0]);
        atomicAdd(&out[srow * 1024 + tcol + 1],       C[nt * 4 + 1]);
        atomicAdd(&out[(srow + 8) * 1024 + tcol],     C[nt * 4 + 2]);
        atomicAdd(&out[(srow + 8) * 1024 + tcol + 1], C[nt * 4 + 3]);
    }
}

// ---------------- launch ----------------
extern "C" void kernel_launch(void* const* d_in, const int* in_sizes, int n_in,
                              void* d_out, int out_size) {
    const float*  photons = (const float*)d_in[0];
    const float2* xy      = (const float2*)d_in[1];
    const float*  zpos    = (const float*)d_in[2];
    const float*  W1      = (const float*)d_in[3];
    const float*  b1      = (const float*)d_in[4];
    const float*  W2      = (const float*)d_in[5];
    const float*  b2      = (const float*)d_in[6];
    const float*  W3      = (const float*)d_in[7];
    const float*  b3      = (const float*)d_in[8];
    float* out = (float*)d_out;

    cudaFuncSetAttribute(mlp_kernel, cudaFuncAttributeMaxDynamicSharedMemorySize, MLP_SMEM);
    cudaFuncSetAttribute(waveform_gemm, cudaFuncAttributeMaxDynamicSharedMemorySize, WV_SMEM);

    zero_kernel<<<64, 256>>>((float4*)out);
    bin_kernel<<<(N_EL + 255) / 256, 256>>>(zpos);
    mlp_kernel<<<MLP_GRID, 256, MLP_SMEM>>>(photons, xy, W1, b1, W2, b2, W3, b3);

    dim3 wgrid(TICKS / 32, WV_NSL);
    waveform_gemm<<<wgrid, 256, WV_SMEM>>>(out);
}